// round 3
// baseline (speedup 1.0000x reference)
#include <cuda_runtime.h>
#include <math.h>

// Problem constants (fixed by the dataset)
#define N_MAX 100000
#define E_MAX 3200000
#define CH 48            // K*H = 3*16

// ---------------- persistent device scratch (static, no runtime alloc) ---------------
__device__ int    g_row[E_MAX];
__device__ int    g_col[E_MAX];
__device__ float  g_deg[N_MAX];
__device__ float  g_dinv[N_MAX];
__device__ int    g_cnt[N_MAX];
__device__ int    g_colptr[N_MAX + 1];
__device__ int    g_wp[N_MAX];
__device__ int    g_csrs[E_MAX];         // src node, grouped by target
__device__ float  g_csrn[E_MAX];         // norm,     grouped by target
__device__ float  g_y[N_MAX];            // y = A_hat @ x
__device__ float  g_z[(size_t)N_MAX * CH];   // state to be propagated (= out @ W)
__device__ float  g_out[(size_t)N_MAX * CH]; // post-epilogue out
__device__ float4 g_s[2][N_MAX];         // conv2 state ping/pong
__device__ float4 g_r2[N_MAX];           // conv2 root+bias per stack
__device__ float  g_bnsum[16];
__device__ float  g_bnsq[16];

// ---------------- preprocessing ----------------
__global__ void k_zero(int n) {
    int i = blockIdx.x * blockDim.x + threadIdx.x;
    if (i < n) { g_deg[i] = 0.f; g_cnt[i] = 0; }
    if (i < 16) { g_bnsum[i] = 0.f; g_bnsq[i] = 0.f; }
}

// edge_index is int32 (JAX default x64-disabled downcasts int64 -> int32)
__global__ void k_pre(const int* __restrict__ ei, const float* __restrict__ attr, int E, int n) {
    int e = blockIdx.x * blockDim.x + threadIdx.x;
    if (e >= E) return;
    int r = ei[e];
    int c = ei[E + e];
    // defensive clamp: convert any bad index into a wrong-answer signal, not a trap
    r = min(max(r, 0), n - 1);
    c = min(max(c, 0), n - 1);
    g_row[e] = r; g_col[e] = c;
    atomicAdd(&g_deg[c], attr[e]);
    atomicAdd(&g_cnt[c], 1);
}

__global__ void k_dinv(int n) {
    int i = blockIdx.x * blockDim.x + threadIdx.x;
    if (i >= n) return;
    float d = g_deg[i];
    g_dinv[i] = (d > 0.f) ? rsqrtf(fmaxf(d, 1e-12f)) : 0.f;
}

// single-block chunked exclusive scan of g_cnt -> g_colptr (+ copy to g_wp)
__global__ void k_scan(int n, int total) {
    __shared__ int ssum[1024];
    int tid = threadIdx.x;
    int chunk = (n + 1023) >> 10;
    int s = tid * chunk;
    int e = min(s + chunk, n);
    int local = 0;
    for (int i = s; i < e; i++) local += g_cnt[i];
    ssum[tid] = local;
    __syncthreads();
    for (int off = 1; off < 1024; off <<= 1) {
        int v = (tid >= off) ? ssum[tid - off] : 0;
        __syncthreads();
        ssum[tid] += v;
        __syncthreads();
    }
    int run = (tid == 0) ? 0 : ssum[tid - 1];
    for (int i = s; i < e; i++) {
        g_colptr[i] = run; g_wp[i] = run;
        run += g_cnt[i];
    }
    if (tid == 1023) g_colptr[n] = total;
}

__global__ void k_scatter(const float* __restrict__ attr, int E) {
    int e = blockIdx.x * blockDim.x + threadIdx.x;
    if (e >= E) return;
    int r = g_row[e], c = g_col[e];
    float nm = g_dinv[r] * attr[e] * g_dinv[c];
    int pos = atomicAdd(&g_wp[c], 1);
    g_csrs[pos] = r;
    g_csrn[pos] = nm;
}

// ---------------- conv1 ----------------
// y = A_hat @ x  (single channel)
__global__ void k_prop1(const float* __restrict__ x, int n) {
    int w = (blockIdx.x * blockDim.x + threadIdx.x) >> 5;
    int lane = threadIdx.x & 31;
    if (w >= n) return;
    int beg = g_colptr[w], end = g_colptr[w + 1];
    float acc = 0.f;
    for (int i = beg + lane; i < end; i += 32) {
        acc += x[g_csrs[i]] * g_csrn[i];
    }
    #pragma unroll
    for (int o = 16; o; o >>= 1) acc += __shfl_xor_sync(0xffffffffu, acc, o);
    if (lane == 0) g_y[w] = acc;
}

// out1 = relu(y*w_init + x*w_root + b); z = out1 @ W   (one thread per (node,stack))
__global__ void k_init1(const float* __restrict__ x,
                        const float* __restrict__ wi, const float* __restrict__ W,
                        const float* __restrict__ wr, const float* __restrict__ b, int n) {
    int idx = blockIdx.x * blockDim.x + threadIdx.x;
    if (idx >= n * 3) return;
    int node = idx / 3, k = idx - node * 3;
    float xv = x[node], yv = g_y[node];
    float o[16];
    #pragma unroll
    for (int h = 0; h < 16; h++) {
        float v = yv * wi[k * 16 + h] + xv * wr[k * 16 + h] + b[k * 16 + h];
        o[h] = fmaxf(v, 0.f);
    }
    float* zp = g_z + (size_t)node * CH + k * 16;
    #pragma unroll
    for (int ho = 0; ho < 16; ho++) {
        float s = 0.f;
        #pragma unroll
        for (int hi = 0; hi < 16; hi++) s += o[hi] * W[k * 256 + hi * 16 + ho];
        zp[ho] = s;
    }
}

// hot kernel: out = relu(A_hat @ z + x*w_root + b), warp per node, 48 channels
__global__ void k_prop48(const float* __restrict__ x,
                         const float* __restrict__ wr, const float* __restrict__ b, int n) {
    int w = (blockIdx.x * blockDim.x + threadIdx.x) >> 5;
    int lane = threadIdx.x & 31;
    if (w >= n) return;
    int beg = g_colptr[w], end = g_colptr[w + 1];
    float a0 = 0.f, a1 = 0.f, a0b = 0.f, a1b = 0.f;
    int i = beg;
    for (; i + 1 < end; i += 2) {
        int s0 = g_csrs[i];
        int s1 = g_csrs[i + 1];
        float n0 = g_csrn[i], n1 = g_csrn[i + 1];
        const float* z0 = g_z + (size_t)s0 * CH;
        const float* z1 = g_z + (size_t)s1 * CH;
        float v00 = z0[lane];
        float v10 = z1[lane];
        float v01 = (lane < 16) ? z0[32 + lane] : 0.f;
        float v11 = (lane < 16) ? z1[32 + lane] : 0.f;
        a0  += v00 * n0;
        a0b += v10 * n1;
        a1  += v01 * n0;
        a1b += v11 * n1;
    }
    if (i < end) {
        int s0 = g_csrs[i];
        float n0 = g_csrn[i];
        const float* z0 = g_z + (size_t)s0 * CH;
        a0 += z0[lane] * n0;
        if (lane < 16) a1 += z0[32 + lane] * n0;
    }
    a0 += a0b; a1 += a1b;

    float xv = x[w];
    float o0 = fmaxf(a0 + xv * wr[lane] + b[lane], 0.f);
    g_out[(size_t)w * CH + lane] = o0;
    if (lane < 16) {
        int c2 = 32 + lane;
        float o1 = fmaxf(a1 + xv * wr[c2] + b[c2], 0.f);
        g_out[(size_t)w * CH + c2] = o1;
    }
}

// z = out @ W per stack
__global__ void k_trans(const float* __restrict__ W, int n) {
    int idx = blockIdx.x * blockDim.x + threadIdx.x;
    if (idx >= n * 3) return;
    int node = idx / 3, k = idx - node * 3;
    const float* op = g_out + (size_t)node * CH + k * 16;
    float o[16];
    #pragma unroll
    for (int h = 0; h < 16; h++) o[h] = op[h];
    float* zp = g_z + (size_t)node * CH + k * 16;
    #pragma unroll
    for (int ho = 0; ho < 16; ho++) {
        float s = 0.f;
        #pragma unroll
        for (int hi = 0; hi < 16; hi++) s += o[hi] * W[k * 256 + hi * 16 + ho];
        zp[ho] = s;
    }
}

// ---------------- batchnorm + conv2 ----------------
__global__ void k_bnstats(int n) {
    int tid = blockIdx.x * blockDim.x + threadIdx.x;
    int stride = gridDim.x * blockDim.x;   // multiple of 16 (blockDim=256)
    float s = 0.f, q = 0.f;
    for (int base = tid; base < n * 16; base += stride) {
        int node = base >> 4;
        int c = base & 15;
        const float* op = g_out + (size_t)node * CH;
        float h = (op[c] + op[16 + c] + op[32 + c]) * (1.f / 3.f);
        s += h; q += h * h;
    }
    atomicAdd(&g_bnsum[tid & 15], s);
    atomicAdd(&g_bnsq[tid & 15], q);
}

__global__ void k_conv2init(const float* __restrict__ bg, const float* __restrict__ bb,
                            const float* __restrict__ w2i, const float* __restrict__ w2r,
                            const float* __restrict__ b2, int n) {
    int node = blockIdx.x * blockDim.x + threadIdx.x;
    if (node >= n) return;
    const float* op = g_out + (size_t)node * CH;
    float invN = 1.f / (float)n;
    float s0 = 0.f, s1 = 0.f, s2 = 0.f;
    float r0 = b2[0], r1 = b2[1], r2 = b2[2];
    #pragma unroll
    for (int c = 0; c < 16; c++) {
        float h = (op[c] + op[16 + c] + op[32 + c]) * (1.f / 3.f);
        float mu = g_bnsum[c] * invN;
        float var = g_bnsq[c] * invN - mu * mu;
        float hb = (h - mu) * rsqrtf(var + 1e-5f) * bg[c] + bb[c];
        hb = fmaxf(hb, 0.f);
        s0 += hb * w2i[c];
        s1 += hb * w2i[16 + c];
        s2 += hb * w2i[32 + c];
        r0 += hb * w2r[c];
        r1 += hb * w2r[16 + c];
        r2 += hb * w2r[32 + c];
    }
    g_s[0][node] = make_float4(s0, s1, s2, 0.f);
    g_r2[node] = make_float4(r0, r1, r2, 0.f);
}

// conv2 propagation step (3 channels = K stacks)
__global__ void k_prop3(int srcIdx, int useW, int finalOut,
                        const float* __restrict__ w2, float* __restrict__ dout, int n) {
    int w = (blockIdx.x * blockDim.x + threadIdx.x) >> 5;
    int lane = threadIdx.x & 31;
    if (w >= n) return;
    const float4* s = g_s[srcIdx];
    int beg = g_colptr[w], end = g_colptr[w + 1];
    float a0 = 0.f, a1 = 0.f, a2 = 0.f;
    for (int i = beg + lane; i < end; i += 32) {
        float nm = g_csrn[i];
        float4 v = s[g_csrs[i]];
        a0 += v.x * nm; a1 += v.y * nm; a2 += v.z * nm;
    }
    #pragma unroll
    for (int o = 16; o; o >>= 1) {
        a0 += __shfl_xor_sync(0xffffffffu, a0, o);
        a1 += __shfl_xor_sync(0xffffffffu, a1, o);
        a2 += __shfl_xor_sync(0xffffffffu, a2, o);
    }
    if (lane == 0) {
        if (useW) {
            a0 *= w2[0]; a1 *= w2[1]; a2 *= w2[2];
        }
        float4 r = g_r2[w];
        a0 += r.x; a1 += r.y; a2 += r.z;
        if (finalOut) {
            float m = (a0 + a1 + a2) * (1.f / 3.f);
            dout[w] = 1.f / (1.f + expf(-m));
        } else {
            g_s[1 - srcIdx][w] = make_float4(a0, a1, a2, 0.f);
        }
    }
}

static inline int cdiv(int a, int b) { return (a + b - 1) / b; }

extern "C" void kernel_launch(void* const* d_in, const int* in_sizes, int n_in,
                              void* d_out, int out_size) {
    const float* x    = (const float*)d_in[0];
    const int*   ei   = (const int*)d_in[1];    // int32! (JAX x64 disabled)
    const float* attr = (const float*)d_in[2];
    // d_in[3] = batch (unused)
    const float* w1i  = (const float*)d_in[4];
    const float* w1   = (const float*)d_in[5];
    const float* w1r  = (const float*)d_in[6];
    const float* b1   = (const float*)d_in[7];
    const float* bg   = (const float*)d_in[8];
    const float* bb   = (const float*)d_in[9];
    const float* w2i  = (const float*)d_in[10];
    const float* w2   = (const float*)d_in[11];
    const float* w2r  = (const float*)d_in[12];
    const float* b2   = (const float*)d_in[13];
    float* out = (float*)d_out;

    int N = in_sizes[0];   // 100000
    int E = in_sizes[2];   // 3200000 (edge_attr element count)

    // ---- preprocessing: degrees, norms, CSR grouped by target ----
    k_zero<<<cdiv(N, 256), 256>>>(N);
    k_pre<<<cdiv(E, 256), 256>>>(ei, attr, E, N);
    k_dinv<<<cdiv(N, 256), 256>>>(N);
    k_scan<<<1, 1024>>>(N, E);
    k_scatter<<<cdiv(E, 256), 256>>>(attr, E);

    // ---- conv1 (K=3, H=16, L=4, relu) ----
    // layer 0 via rank-1 shortcut: y = A_hat x, then out1 analytic, z1 = out1 @ W
    k_prop1<<<cdiv(N * 32, 256), 256>>>(x, N);
    k_init1<<<cdiv(N * 3, 256), 256>>>(x, w1i, w1, w1r, b1, N);
    for (int t = 1; t <= 3; t++) {
        k_prop48<<<cdiv(N, 8), 256>>>(x, w1r, b1, N);
        if (t < 3) k_trans<<<cdiv(N * 3, 256), 256>>>(w1, N);
    }

    // ---- batchnorm (batch stats) + relu, conv2 init state + root ----
    k_bnstats<<<232, 256>>>(N);
    k_conv2init<<<cdiv(N, 256), 256>>>(bg, bb, w2i, w2r, b2, N);

    // ---- conv2 (K=3, C=1, L=4, no act), then mean over K + sigmoid ----
    k_prop3<<<cdiv(N, 8), 256>>>(0, 0, 0, w2, out, N);  // s0 -> s1  (t=0, no w2)
    k_prop3<<<cdiv(N, 8), 256>>>(1, 1, 0, w2, out, N);  // s1 -> s0
    k_prop3<<<cdiv(N, 8), 256>>>(0, 1, 0, w2, out, N);  // s0 -> s1
    k_prop3<<<cdiv(N, 8), 256>>>(1, 1, 1, w2, out, N);  // s1 -> sigmoid -> d_out
}

// round 4
// speedup vs baseline: 1.2693x; 1.2693x over previous
#include <cuda_runtime.h>
#include <math.h>

// Problem constants (fixed by the dataset)
#define N_MAX 100000
#define E_MAX 3200000
#define CH 48            // K*H = 3*16
#define SCAN_CHUNK 1024  // counters per block in hierarchical scan
#define SCAN_NB ((N_MAX + SCAN_CHUNK - 1) / SCAN_CHUNK)   // 98

// ---------------- persistent device scratch (static, no runtime alloc) ---------------
__device__ int    g_row[E_MAX];
__device__ int    g_col[E_MAX];
__device__ float  g_deg[N_MAX];
__device__ float  g_dinv[N_MAX];
__device__ int    g_cnt[N_MAX];
__device__ int    g_colptr[N_MAX + 1];
__device__ int    g_wp[N_MAX];
__device__ int    g_bsum[SCAN_NB];       // per-block sums for hierarchical scan
__device__ int    g_boff[SCAN_NB];       // exclusive prefix of block sums
__device__ int    g_csrs[E_MAX];         // src node, grouped by target
__device__ float  g_csrn[E_MAX];         // norm,     grouped by target
__device__ float  g_y[N_MAX];            // y = A_hat @ x
__device__ float  g_z[(size_t)N_MAX * CH];   // state to be propagated (= out @ W)
__device__ float  g_out[(size_t)N_MAX * CH]; // post-epilogue out
__device__ float4 g_s[2][N_MAX];         // conv2 state ping/pong
__device__ float4 g_r2[N_MAX];           // conv2 root+bias per stack
__device__ float  g_bnsum[16];
__device__ float  g_bnsq[16];

// ---------------- preprocessing ----------------
__global__ void k_zero(int n) {
    int i = blockIdx.x * blockDim.x + threadIdx.x;
    if (i < n) { g_deg[i] = 0.f; g_cnt[i] = 0; }
    if (i < 16) { g_bnsum[i] = 0.f; g_bnsq[i] = 0.f; }
}

// edge_index is int32 (JAX default x64-disabled downcasts int64 -> int32)
__global__ void k_pre(const int* __restrict__ ei, const float* __restrict__ attr, int E, int n) {
    int e = blockIdx.x * blockDim.x + threadIdx.x;
    if (e >= E) return;
    int r = ei[e];
    int c = ei[E + e];
    r = min(max(r, 0), n - 1);
    c = min(max(c, 0), n - 1);
    g_row[e] = r; g_col[e] = c;
    atomicAdd(&g_deg[c], attr[e]);
    atomicAdd(&g_cnt[c], 1);
}

__global__ void k_dinv(int n) {
    int i = blockIdx.x * blockDim.x + threadIdx.x;
    if (i >= n) return;
    float d = g_deg[i];
    g_dinv[i] = (d > 0.f) ? rsqrtf(fmaxf(d, 1e-12f)) : 0.f;
}

// ---- hierarchical exclusive scan of g_cnt -> g_colptr / g_wp ----
// stage 1: per-block sums (256 threads, 4 counters each)
__global__ void k_blocksum(int n) {
    __shared__ int sh[256];
    int base = blockIdx.x * SCAN_CHUNK;
    int tid = threadIdx.x;
    int s = 0;
    #pragma unroll
    for (int j = 0; j < 4; j++) {
        int i = base + tid * 4 + j;
        if (i < n) s += g_cnt[i];
    }
    sh[tid] = s;
    __syncthreads();
    for (int off = 128; off; off >>= 1) {
        if (tid < off) sh[tid] += sh[tid + off];
        __syncthreads();
    }
    if (tid == 0) g_bsum[blockIdx.x] = sh[0];
}

// stage 2: scan the block sums (one small block)
__global__ void k_scanb(int nb) {
    __shared__ int sh[SCAN_NB];
    int tid = threadIdx.x;
    if (tid < nb) sh[tid] = g_bsum[tid];
    __syncthreads();
    if (tid == 0) {
        int run = 0;
        for (int i = 0; i < nb; i++) { int v = sh[i]; sh[i] = run; run += v; }
    }
    __syncthreads();
    if (tid < nb) g_boff[tid] = sh[tid];
}

// stage 3: in-block exclusive scan + offset, write colptr/wp
__global__ void k_fillptr(int n, int total) {
    __shared__ int sh[256];
    int base = blockIdx.x * SCAN_CHUNK;
    int tid = threadIdx.x;
    int c[4];
    int s = 0;
    #pragma unroll
    for (int j = 0; j < 4; j++) {
        int i = base + tid * 4 + j;
        c[j] = (i < n) ? g_cnt[i] : 0;
        s += c[j];
    }
    sh[tid] = s;
    __syncthreads();
    // exclusive scan of 256 thread sums (Hillis-Steele then shift)
    for (int off = 1; off < 256; off <<= 1) {
        int v = (tid >= off) ? sh[tid - off] : 0;
        __syncthreads();
        sh[tid] += v;
        __syncthreads();
    }
    int run = g_boff[blockIdx.x] + ((tid > 0) ? sh[tid - 1] : 0);
    #pragma unroll
    for (int j = 0; j < 4; j++) {
        int i = base + tid * 4 + j;
        if (i < n) { g_colptr[i] = run; g_wp[i] = run; run += c[j]; }
    }
    if (blockIdx.x == 0 && tid == 0) g_colptr[n] = total;
}

__global__ void k_scatter(const float* __restrict__ attr, int E) {
    int e = blockIdx.x * blockDim.x + threadIdx.x;
    if (e >= E) return;
    int r = g_row[e], c = g_col[e];
    float nm = g_dinv[r] * attr[e] * g_dinv[c];
    int pos = atomicAdd(&g_wp[c], 1);
    g_csrs[pos] = r;
    g_csrn[pos] = nm;
}

// ---------------- conv1 ----------------
// y = A_hat @ x  (single channel)
__global__ void k_prop1(const float* __restrict__ x, int n) {
    int w = (blockIdx.x * blockDim.x + threadIdx.x) >> 5;
    int lane = threadIdx.x & 31;
    if (w >= n) return;
    int beg = g_colptr[w], end = g_colptr[w + 1];
    float acc = 0.f;
    for (int i = beg + lane; i < end; i += 32) {
        acc += x[g_csrs[i]] * g_csrn[i];
    }
    #pragma unroll
    for (int o = 16; o; o >>= 1) acc += __shfl_xor_sync(0xffffffffu, acc, o);
    if (lane == 0) g_y[w] = acc;
}

// out1 = relu(y*w_init + x*w_root + b); z = out1 @ W   (one thread per (node,stack))
__global__ void k_init1(const float* __restrict__ x,
                        const float* __restrict__ wi, const float* __restrict__ W,
                        const float* __restrict__ wr, const float* __restrict__ b, int n) {
    int idx = blockIdx.x * blockDim.x + threadIdx.x;
    if (idx >= n * 3) return;
    int node = idx / 3, k = idx - node * 3;
    float xv = x[node], yv = g_y[node];
    float o[16];
    #pragma unroll
    for (int h = 0; h < 16; h++) {
        float v = yv * wi[k * 16 + h] + xv * wr[k * 16 + h] + b[k * 16 + h];
        o[h] = fmaxf(v, 0.f);
    }
    float* zp = g_z + (size_t)node * CH + k * 16;
    #pragma unroll
    for (int ho = 0; ho < 16; ho++) {
        float s = 0.f;
        #pragma unroll
        for (int hi = 0; hi < 16; hi++) s += o[hi] * W[k * 256 + hi * 16 + ho];
        zp[ho] = s;
    }
}

// hot kernel: out = relu(A_hat @ z + x*w_root + b), warp per node, 48 channels
__global__ void k_prop48(const float* __restrict__ x,
                         const float* __restrict__ wr, const float* __restrict__ b, int n) {
    int w = (blockIdx.x * blockDim.x + threadIdx.x) >> 5;
    int lane = threadIdx.x & 31;
    if (w >= n) return;
    int beg = g_colptr[w], end = g_colptr[w + 1];
    float a0 = 0.f, a1 = 0.f, a0b = 0.f, a1b = 0.f;
    int i = beg;
    for (; i + 1 < end; i += 2) {
        int s0 = g_csrs[i];
        int s1 = g_csrs[i + 1];
        float n0 = g_csrn[i], n1 = g_csrn[i + 1];
        const float* z0 = g_z + (size_t)s0 * CH;
        const float* z1 = g_z + (size_t)s1 * CH;
        float v00 = z0[lane];
        float v10 = z1[lane];
        float v01 = (lane < 16) ? z0[32 + lane] : 0.f;
        float v11 = (lane < 16) ? z1[32 + lane] : 0.f;
        a0  += v00 * n0;
        a0b += v10 * n1;
        a1  += v01 * n0;
        a1b += v11 * n1;
    }
    if (i < end) {
        int s0 = g_csrs[i];
        float n0 = g_csrn[i];
        const float* z0 = g_z + (size_t)s0 * CH;
        a0 += z0[lane] * n0;
        if (lane < 16) a1 += z0[32 + lane] * n0;
    }
    a0 += a0b; a1 += a1b;

    float xv = x[w];
    float o0 = fmaxf(a0 + xv * wr[lane] + b[lane], 0.f);
    g_out[(size_t)w * CH + lane] = o0;
    if (lane < 16) {
        int c2 = 32 + lane;
        float o1 = fmaxf(a1 + xv * wr[c2] + b[c2], 0.f);
        g_out[(size_t)w * CH + c2] = o1;
    }
}

// z = out @ W per stack
__global__ void k_trans(const float* __restrict__ W, int n) {
    int idx = blockIdx.x * blockDim.x + threadIdx.x;
    if (idx >= n * 3) return;
    int node = idx / 3, k = idx - node * 3;
    const float* op = g_out + (size_t)node * CH + k * 16;
    float o[16];
    #pragma unroll
    for (int h = 0; h < 16; h++) o[h] = op[h];
    float* zp = g_z + (size_t)node * CH + k * 16;
    #pragma unroll
    for (int ho = 0; ho < 16; ho++) {
        float s = 0.f;
        #pragma unroll
        for (int hi = 0; hi < 16; hi++) s += o[hi] * W[k * 256 + hi * 16 + ho];
        zp[ho] = s;
    }
}

// ---------------- batchnorm + conv2 ----------------
__global__ void k_bnstats(int n) {
    int tid = blockIdx.x * blockDim.x + threadIdx.x;
    int stride = gridDim.x * blockDim.x;   // multiple of 16 (blockDim=256)
    float s = 0.f, q = 0.f;
    for (int base = tid; base < n * 16; base += stride) {
        int node = base >> 4;
        int c = base & 15;
        const float* op = g_out + (size_t)node * CH;
        float h = (op[c] + op[16 + c] + op[32 + c]) * (1.f / 3.f);
        s += h; q += h * h;
    }
    atomicAdd(&g_bnsum[tid & 15], s);
    atomicAdd(&g_bnsq[tid & 15], q);
}

__global__ void k_conv2init(const float* __restrict__ bg, const float* __restrict__ bb,
                            const float* __restrict__ w2i, const float* __restrict__ w2r,
                            const float* __restrict__ b2, int n) {
    int node = blockIdx.x * blockDim.x + threadIdx.x;
    if (node >= n) return;
    const float* op = g_out + (size_t)node * CH;
    float invN = 1.f / (float)n;
    float s0 = 0.f, s1 = 0.f, s2 = 0.f;
    float r0 = b2[0], r1 = b2[1], r2 = b2[2];
    #pragma unroll
    for (int c = 0; c < 16; c++) {
        float h = (op[c] + op[16 + c] + op[32 + c]) * (1.f / 3.f);
        float mu = g_bnsum[c] * invN;
        float var = g_bnsq[c] * invN - mu * mu;
        float hb = (h - mu) * rsqrtf(var + 1e-5f) * bg[c] + bb[c];
        hb = fmaxf(hb, 0.f);
        s0 += hb * w2i[c];
        s1 += hb * w2i[16 + c];
        s2 += hb * w2i[32 + c];
        r0 += hb * w2r[c];
        r1 += hb * w2r[16 + c];
        r2 += hb * w2r[32 + c];
    }
    g_s[0][node] = make_float4(s0, s1, s2, 0.f);
    g_r2[node] = make_float4(r0, r1, r2, 0.f);
}

// conv2 propagation step (3 channels = K stacks)
__global__ void k_prop3(int srcIdx, int useW, int finalOut,
                        const float* __restrict__ w2, float* __restrict__ dout, int n) {
    int w = (blockIdx.x * blockDim.x + threadIdx.x) >> 5;
    int lane = threadIdx.x & 31;
    if (w >= n) return;
    const float4* s = g_s[srcIdx];
    int beg = g_colptr[w], end = g_colptr[w + 1];
    float a0 = 0.f, a1 = 0.f, a2 = 0.f;
    for (int i = beg + lane; i < end; i += 32) {
        float nm = g_csrn[i];
        float4 v = s[g_csrs[i]];
        a0 += v.x * nm; a1 += v.y * nm; a2 += v.z * nm;
    }
    #pragma unroll
    for (int o = 16; o; o >>= 1) {
        a0 += __shfl_xor_sync(0xffffffffu, a0, o);
        a1 += __shfl_xor_sync(0xffffffffu, a1, o);
        a2 += __shfl_xor_sync(0xffffffffu, a2, o);
    }
    if (lane == 0) {
        if (useW) {
            a0 *= w2[0]; a1 *= w2[1]; a2 *= w2[2];
        }
        float4 r = g_r2[w];
        a0 += r.x; a1 += r.y; a2 += r.z;
        if (finalOut) {
            float m = (a0 + a1 + a2) * (1.f / 3.f);
            dout[w] = 1.f / (1.f + expf(-m));
        } else {
            g_s[1 - srcIdx][w] = make_float4(a0, a1, a2, 0.f);
        }
    }
}

static inline int cdiv(int a, int b) { return (a + b - 1) / b; }

extern "C" void kernel_launch(void* const* d_in, const int* in_sizes, int n_in,
                              void* d_out, int out_size) {
    const float* x    = (const float*)d_in[0];
    const int*   ei   = (const int*)d_in[1];    // int32! (JAX x64 disabled)
    const float* attr = (const float*)d_in[2];
    // d_in[3] = batch (unused)
    const float* w1i  = (const float*)d_in[4];
    const float* w1   = (const float*)d_in[5];
    const float* w1r  = (const float*)d_in[6];
    const float* b1   = (const float*)d_in[7];
    const float* bg   = (const float*)d_in[8];
    const float* bb   = (const float*)d_in[9];
    const float* w2i  = (const float*)d_in[10];
    const float* w2   = (const float*)d_in[11];
    const float* w2r  = (const float*)d_in[12];
    const float* b2   = (const float*)d_in[13];
    float* out = (float*)d_out;

    int N = in_sizes[0];   // 100000
    int E = in_sizes[2];   // 3200000 (edge_attr element count)
    int nb = cdiv(N, SCAN_CHUNK);

    // ---- preprocessing: degrees, norms, CSR grouped by target ----
    k_zero<<<cdiv(N, 256), 256>>>(N);
    k_pre<<<cdiv(E, 256), 256>>>(ei, attr, E, N);
    k_dinv<<<cdiv(N, 256), 256>>>(N);
    k_blocksum<<<nb, 256>>>(N);
    k_scanb<<<1, 128>>>(nb);
    k_fillptr<<<nb, 256>>>(N, E);
    k_scatter<<<cdiv(E, 256), 256>>>(attr, E);

    // ---- conv1 (K=3, H=16, L=4, relu) ----
    // layer 0 via rank-1 shortcut: y = A_hat x, then out1 analytic, z1 = out1 @ W
    k_prop1<<<cdiv(N * 32, 256), 256>>>(x, N);
    k_init1<<<cdiv(N * 3, 256), 256>>>(x, w1i, w1, w1r, b1, N);
    for (int t = 1; t <= 3; t++) {
        k_prop48<<<cdiv(N, 8), 256>>>(x, w1r, b1, N);
        if (t < 3) k_trans<<<cdiv(N * 3, 256), 256>>>(w1, N);
    }

    // ---- batchnorm (batch stats) + relu, conv2 init state + root ----
    k_bnstats<<<232, 256>>>(N);
    k_conv2init<<<cdiv(N, 256), 256>>>(bg, bb, w2i, w2r, b2, N);

    // ---- conv2 (K=3, C=1, L=4, no act), then mean over K + sigmoid ----
    k_prop3<<<cdiv(N, 8), 256>>>(0, 0, 0, w2, out, N);  // s0 -> s1  (t=0, no w2)
    k_prop3<<<cdiv(N, 8), 256>>>(1, 1, 0, w2, out, N);  // s1 -> s0
    k_prop3<<<cdiv(N, 8), 256>>>(0, 1, 0, w2, out, N);  // s0 -> s1
    k_prop3<<<cdiv(N, 8), 256>>>(1, 1, 1, w2, out, N);  // s1 -> sigmoid -> d_out
}

// round 5
// speedup vs baseline: 1.2790x; 1.0076x over previous
#include <cuda_runtime.h>
#include <cuda_fp16.h>
#include <math.h>

// Problem constants (fixed by the dataset)
#define N_MAX 100000
#define E_MAX 3200000
#define CH 48            // K*H = 3*16
#define ZW 24            // half2 words per node (48 channels)
#define SCAN_CHUNK 1024
#define SCAN_NB ((N_MAX + SCAN_CHUNK - 1) / SCAN_CHUNK)   // 98

// ---------------- persistent device scratch ----------------
__device__ float   g_deg[N_MAX];
__device__ float   g_dinv[N_MAX];
__device__ int     g_cnt[N_MAX];
__device__ int     g_colptr[N_MAX + 1];
__device__ int     g_epos[E_MAX];        // per-edge rank within its target bucket
__device__ int     g_bsum[SCAN_NB];
__device__ int     g_boff[SCAN_NB];
__device__ uint2   g_csr[E_MAX];         // {src, norm-bits} grouped by target
__device__ float   g_y[N_MAX];           // y = A_hat @ x
__device__ __half2 g_z2[(size_t)N_MAX * ZW];  // propagated state, half2-packed
__device__ float   g_out[(size_t)N_MAX * CH]; // post-epilogue out (fp32)
__device__ float4  g_s[2][N_MAX];        // conv2 state ping/pong
__device__ float4  g_r2[N_MAX];          // conv2 root+bias per stack
__device__ float   g_bnsum[16];
__device__ float   g_bnsq[16];

// ---------------- preprocessing ----------------
__global__ void k_zero(int n) {
    int i = blockIdx.x * blockDim.x + threadIdx.x;
    if (i < n) { g_deg[i] = 0.f; g_cnt[i] = 0; }
    if (i < 16) { g_bnsum[i] = 0.f; g_bnsq[i] = 0.f; }
}

// edge_index is int32. Record each edge's bucket rank from the cnt atomic.
__global__ void k_pre(const int* __restrict__ ei, const float* __restrict__ attr, int E, int n) {
    int e = blockIdx.x * blockDim.x + threadIdx.x;
    if (e >= E) return;
    int c = ei[E + e];
    c = min(max(c, 0), n - 1);
    atomicAdd(&g_deg[c], attr[e]);
    g_epos[e] = atomicAdd(&g_cnt[c], 1);
}

// fused: dinv for this block's 1024 nodes + block sum of cnt
__global__ void k_dinv_blocksum(int n) {
    __shared__ int sh[256];
    int base = blockIdx.x * SCAN_CHUNK;
    int tid = threadIdx.x;
    int s = 0;
    #pragma unroll
    for (int j = 0; j < 4; j++) {
        int i = base + tid * 4 + j;
        if (i < n) {
            float d = g_deg[i];
            g_dinv[i] = (d > 0.f) ? rsqrtf(fmaxf(d, 1e-12f)) : 0.f;
            s += g_cnt[i];
        }
    }
    sh[tid] = s;
    __syncthreads();
    for (int off = 128; off; off >>= 1) {
        if (tid < off) sh[tid] += sh[tid + off];
        __syncthreads();
    }
    if (tid == 0) g_bsum[blockIdx.x] = sh[0];
}

__global__ void k_scanb(int nb) {
    __shared__ int sh[SCAN_NB];
    int tid = threadIdx.x;
    if (tid < nb) sh[tid] = g_bsum[tid];
    __syncthreads();
    if (tid == 0) {
        int run = 0;
        for (int i = 0; i < nb; i++) { int v = sh[i]; sh[i] = run; run += v; }
    }
    __syncthreads();
    if (tid < nb) g_boff[tid] = sh[tid];
}

__global__ void k_fillptr(int n, int total) {
    __shared__ int sh[256];
    int base = blockIdx.x * SCAN_CHUNK;
    int tid = threadIdx.x;
    int c[4];
    int s = 0;
    #pragma unroll
    for (int j = 0; j < 4; j++) {
        int i = base + tid * 4 + j;
        c[j] = (i < n) ? g_cnt[i] : 0;
        s += c[j];
    }
    sh[tid] = s;
    __syncthreads();
    for (int off = 1; off < 256; off <<= 1) {
        int v = (tid >= off) ? sh[tid - off] : 0;
        __syncthreads();
        sh[tid] += v;
        __syncthreads();
    }
    int run = g_boff[blockIdx.x] + ((tid > 0) ? sh[tid - 1] : 0);
    #pragma unroll
    for (int j = 0; j < 4; j++) {
        int i = base + tid * 4 + j;
        if (i < n) { g_colptr[i] = run; run += c[j]; }
    }
    if (blockIdx.x == 0 && tid == 0) g_colptr[n] = total;
}

// no atomics: position = colptr[c] + epos[e]
__global__ void k_scatter(const int* __restrict__ ei, const float* __restrict__ attr, int E, int n) {
    int e = blockIdx.x * blockDim.x + threadIdx.x;
    if (e >= E) return;
    int r = ei[e];
    int c = ei[E + e];
    r = min(max(r, 0), n - 1);
    c = min(max(c, 0), n - 1);
    float nm = g_dinv[r] * attr[e] * g_dinv[c];
    g_csr[g_colptr[c] + g_epos[e]] = make_uint2((unsigned)r, __float_as_uint(nm));
}

// ---------------- conv1 ----------------
// y = A_hat @ x  (single channel)
__global__ void k_prop1(const float* __restrict__ x, int n) {
    int w = (blockIdx.x * blockDim.x + threadIdx.x) >> 5;
    int lane = threadIdx.x & 31;
    if (w >= n) return;
    int beg = g_colptr[w], end = g_colptr[w + 1];
    float acc = 0.f;
    for (int i = beg + lane; i < end; i += 32) {
        uint2 e = g_csr[i];
        acc += x[e.x] * __uint_as_float(e.y);
    }
    #pragma unroll
    for (int o = 16; o; o >>= 1) acc += __shfl_xor_sync(0xffffffffu, acc, o);
    if (lane == 0) g_y[w] = acc;
}

// out1 = relu(y*w_init + x*w_root + b); z = out1 @ W, stored half2
__global__ void k_init1(const float* __restrict__ x,
                        const float* __restrict__ wi, const float* __restrict__ W,
                        const float* __restrict__ wr, const float* __restrict__ b, int n) {
    int idx = blockIdx.x * blockDim.x + threadIdx.x;
    if (idx >= n * 3) return;
    int node = idx / 3, k = idx - node * 3;
    float xv = x[node], yv = g_y[node];
    float o[16];
    #pragma unroll
    for (int h = 0; h < 16; h++) {
        float v = yv * wi[k * 16 + h] + xv * wr[k * 16 + h] + b[k * 16 + h];
        o[h] = fmaxf(v, 0.f);
    }
    __half2* zp = g_z2 + (size_t)node * ZW + k * 8;
    #pragma unroll
    for (int j = 0; j < 8; j++) {
        float s0 = 0.f, s1 = 0.f;
        #pragma unroll
        for (int hi = 0; hi < 16; hi++) {
            s0 += o[hi] * W[k * 256 + hi * 16 + 2 * j];
            s1 += o[hi] * W[k * 256 + hi * 16 + 2 * j + 1];
        }
        zp[j] = __floats2half2_rn(s0, s1);
    }
}

// hot kernel: out = relu(A_hat @ z + x*w_root + b)
// warp per node; lane < 24 owns channels {2*lane, 2*lane+1}; one half2 load per edge
__global__ void k_prop48(const float* __restrict__ x,
                         const float* __restrict__ wr, const float* __restrict__ b, int n) {
    int w = (blockIdx.x * blockDim.x + threadIdx.x) >> 5;
    int lane = threadIdx.x & 31;
    if (w >= n) return;
    int beg = g_colptr[w], end = g_colptr[w + 1];
    bool act = lane < ZW;
    float a0 = 0.f, a1 = 0.f, c0a = 0.f, c1a = 0.f;
    int i = beg;
    for (; i + 1 < end; i += 2) {
        uint2 e0 = g_csr[i];
        uint2 e1 = g_csr[i + 1];
        float n0 = __uint_as_float(e0.y), n1 = __uint_as_float(e1.y);
        if (act) {
            float2 v0 = __half22float2(g_z2[(size_t)e0.x * ZW + lane]);
            float2 v1 = __half22float2(g_z2[(size_t)e1.x * ZW + lane]);
            a0  += v0.x * n0; a1  += v0.y * n0;
            c0a += v1.x * n1; c1a += v1.y * n1;
        }
    }
    if (i < end) {
        uint2 e0 = g_csr[i];
        float n0 = __uint_as_float(e0.y);
        if (act) {
            float2 v0 = __half22float2(g_z2[(size_t)e0.x * ZW + lane]);
            a0 += v0.x * n0; a1 += v0.y * n0;
        }
    }
    a0 += c0a; a1 += c1a;
    if (act) {
        float xv = x[w];
        int c0 = 2 * lane;
        float o0 = fmaxf(a0 + xv * wr[c0]     + b[c0],     0.f);
        float o1 = fmaxf(a1 + xv * wr[c0 + 1] + b[c0 + 1], 0.f);
        *(float2*)&g_out[(size_t)w * CH + c0] = make_float2(o0, o1);
    }
}

// z = out @ W per stack, stored half2
__global__ void k_trans(const float* __restrict__ W, int n) {
    int idx = blockIdx.x * blockDim.x + threadIdx.x;
    if (idx >= n * 3) return;
    int node = idx / 3, k = idx - node * 3;
    const float* op = g_out + (size_t)node * CH + k * 16;
    float o[16];
    #pragma unroll
    for (int h = 0; h < 16; h++) o[h] = op[h];
    __half2* zp = g_z2 + (size_t)node * ZW + k * 8;
    #pragma unroll
    for (int j = 0; j < 8; j++) {
        float s0 = 0.f, s1 = 0.f;
        #pragma unroll
        for (int hi = 0; hi < 16; hi++) {
            s0 += o[hi] * W[k * 256 + hi * 16 + 2 * j];
            s1 += o[hi] * W[k * 256 + hi * 16 + 2 * j + 1];
        }
        zp[j] = __floats2half2_rn(s0, s1);
    }
}

// ---------------- batchnorm + conv2 ----------------
__global__ void k_bnstats(int n) {
    int tid = blockIdx.x * blockDim.x + threadIdx.x;
    int stride = gridDim.x * blockDim.x;
    float s = 0.f, q = 0.f;
    for (int base = tid; base < n * 16; base += stride) {
        int node = base >> 4;
        int c = base & 15;
        const float* op = g_out + (size_t)node * CH;
        float h = (op[c] + op[16 + c] + op[32 + c]) * (1.f / 3.f);
        s += h; q += h * h;
    }
    atomicAdd(&g_bnsum[tid & 15], s);
    atomicAdd(&g_bnsq[tid & 15], q);
}

__global__ void k_conv2init(const float* __restrict__ bg, const float* __restrict__ bb,
                            const float* __restrict__ w2i, const float* __restrict__ w2r,
                            const float* __restrict__ b2, int n) {
    int node = blockIdx.x * blockDim.x + threadIdx.x;
    if (node >= n) return;
    const float* op = g_out + (size_t)node * CH;
    float invN = 1.f / (float)n;
    float s0 = 0.f, s1 = 0.f, s2 = 0.f;
    float r0 = b2[0], r1 = b2[1], r2 = b2[2];
    #pragma unroll
    for (int c = 0; c < 16; c++) {
        float h = (op[c] + op[16 + c] + op[32 + c]) * (1.f / 3.f);
        float mu = g_bnsum[c] * invN;
        float var = g_bnsq[c] * invN - mu * mu;
        float hb = (h - mu) * rsqrtf(var + 1e-5f) * bg[c] + bb[c];
        hb = fmaxf(hb, 0.f);
        s0 += hb * w2i[c];
        s1 += hb * w2i[16 + c];
        s2 += hb * w2i[32 + c];
        r0 += hb * w2r[c];
        r1 += hb * w2r[16 + c];
        r2 += hb * w2r[32 + c];
    }
    g_s[0][node] = make_float4(s0, s1, s2, 0.f);
    g_r2[node] = make_float4(r0, r1, r2, 0.f);
}

__global__ void k_prop3(int srcIdx, int useW, int finalOut,
                        const float* __restrict__ w2, float* __restrict__ dout, int n) {
    int w = (blockIdx.x * blockDim.x + threadIdx.x) >> 5;
    int lane = threadIdx.x & 31;
    if (w >= n) return;
    const float4* s = g_s[srcIdx];
    int beg = g_colptr[w], end = g_colptr[w + 1];
    float a0 = 0.f, a1 = 0.f, a2 = 0.f;
    for (int i = beg + lane; i < end; i += 32) {
        uint2 e = g_csr[i];
        float nm = __uint_as_float(e.y);
        float4 v = s[e.x];
        a0 += v.x * nm; a1 += v.y * nm; a2 += v.z * nm;
    }
    #pragma unroll
    for (int o = 16; o; o >>= 1) {
        a0 += __shfl_xor_sync(0xffffffffu, a0, o);
        a1 += __shfl_xor_sync(0xffffffffu, a1, o);
        a2 += __shfl_xor_sync(0xffffffffu, a2, o);
    }
    if (lane == 0) {
        if (useW) { a0 *= w2[0]; a1 *= w2[1]; a2 *= w2[2]; }
        float4 r = g_r2[w];
        a0 += r.x; a1 += r.y; a2 += r.z;
        if (finalOut) {
            float m = (a0 + a1 + a2) * (1.f / 3.f);
            dout[w] = 1.f / (1.f + expf(-m));
        } else {
            g_s[1 - srcIdx][w] = make_float4(a0, a1, a2, 0.f);
        }
    }
}

static inline int cdiv(int a, int b) { return (a + b - 1) / b; }

extern "C" void kernel_launch(void* const* d_in, const int* in_sizes, int n_in,
                              void* d_out, int out_size) {
    const float* x    = (const float*)d_in[0];
    const int*   ei   = (const int*)d_in[1];    // int32 (JAX x64 disabled)
    const float* attr = (const float*)d_in[2];
    const float* w1i  = (const float*)d_in[4];
    const float* w1   = (const float*)d_in[5];
    const float* w1r  = (const float*)d_in[6];
    const float* b1   = (const float*)d_in[7];
    const float* bg   = (const float*)d_in[8];
    const float* bb   = (const float*)d_in[9];
    const float* w2i  = (const float*)d_in[10];
    const float* w2   = (const float*)d_in[11];
    const float* w2r  = (const float*)d_in[12];
    const float* b2   = (const float*)d_in[13];
    float* out = (float*)d_out;

    int N = in_sizes[0];   // 100000
    int E = in_sizes[2];   // 3200000
    int nb = cdiv(N, SCAN_CHUNK);

    // ---- preprocessing: degrees, norms, CSR grouped by target ----
    k_zero<<<cdiv(N, 256), 256>>>(N);
    k_pre<<<cdiv(E, 256), 256>>>(ei, attr, E, N);
    k_dinv_blocksum<<<nb, 256>>>(N);
    k_scanb<<<1, 128>>>(nb);
    k_fillptr<<<nb, 256>>>(N, E);
    k_scatter<<<cdiv(E, 256), 256>>>(ei, attr, E, N);

    // ---- conv1 (K=3, H=16, L=4, relu) ----
    k_prop1<<<cdiv(N * 32, 256), 256>>>(x, N);
    k_init1<<<cdiv(N * 3, 256), 256>>>(x, w1i, w1, w1r, b1, N);
    for (int t = 1; t <= 3; t++) {
        k_prop48<<<cdiv(N, 8), 256>>>(x, w1r, b1, N);
        if (t < 3) k_trans<<<cdiv(N * 3, 256), 256>>>(w1, N);
    }

    // ---- batchnorm + relu, conv2 init ----
    k_bnstats<<<232, 256>>>(N);
    k_conv2init<<<cdiv(N, 256), 256>>>(bg, bb, w2i, w2r, b2, N);

    // ---- conv2 (K=3, C=1, L=4, no act) + mean + sigmoid ----
    k_prop3<<<cdiv(N, 8), 256>>>(0, 0, 0, w2, out, N);
    k_prop3<<<cdiv(N, 8), 256>>>(1, 1, 0, w2, out, N);
    k_prop3<<<cdiv(N, 8), 256>>>(0, 1, 0, w2, out, N);
    k_prop3<<<cdiv(N, 8), 256>>>(1, 1, 1, w2, out, N);
}

// round 6
// speedup vs baseline: 1.3796x; 1.0786x over previous
#include <cuda_runtime.h>
#include <cuda_fp16.h>
#include <math.h>

// Problem constants (fixed by the dataset)
#define N_MAX 100000
#define E_MAX 3200000
#define CH 48            // K*H = 3*16
#define ZSTRIDE 32       // half2 words per node (24 used + 8 pad = 128B line)
#define SCAN_CHUNK 1024
#define SCAN_NB ((N_MAX + SCAN_CHUNK - 1) / SCAN_CHUNK)   // 98

// ---------------- persistent device scratch ----------------
__device__ float   g_deg[N_MAX];
__device__ float   g_dinv[N_MAX];
__device__ int     g_cnt[N_MAX];
__device__ int     g_colptr[N_MAX + 1];
__device__ int     g_epos[E_MAX];        // per-edge rank within its target bucket
__device__ int     g_bsum[SCAN_NB];
__device__ int     g_boff[SCAN_NB];
__device__ uint2   g_csr[E_MAX];         // {src, norm-bits} grouped by target
__device__ float   g_y[N_MAX];           // y = A_hat @ x
__device__ __align__(16) __half2 g_z2[(size_t)N_MAX * ZSTRIDE]; // padded state
__device__ float   g_out[(size_t)N_MAX * CH]; // post-epilogue out (fp32)
__device__ float4  g_s[2][N_MAX];        // conv2 state ping/pong
__device__ float4  g_r2[N_MAX];          // conv2 root+bias per stack
__device__ float   g_bnsum[16];
__device__ float   g_bnsq[16];

// ---------------- preprocessing ----------------
__global__ void k_zero(int n) {
    int i = blockIdx.x * blockDim.x + threadIdx.x;
    if (i < n) { g_deg[i] = 0.f; g_cnt[i] = 0; }
    if (i < 16) { g_bnsum[i] = 0.f; g_bnsq[i] = 0.f; }
}

// edge_index is int32. Record each edge's bucket rank from the cnt atomic.
__global__ void k_pre(const int* __restrict__ ei, const float* __restrict__ attr, int E, int n) {
    int e = blockIdx.x * blockDim.x + threadIdx.x;
    if (e >= E) return;
    int c = ei[E + e];
    c = min(max(c, 0), n - 1);
    atomicAdd(&g_deg[c], attr[e]);
    g_epos[e] = atomicAdd(&g_cnt[c], 1);
}

// fused: dinv for this block's 1024 nodes + block sum of cnt
__global__ void k_dinv_blocksum(int n) {
    __shared__ int sh[256];
    int base = blockIdx.x * SCAN_CHUNK;
    int tid = threadIdx.x;
    int s = 0;
    #pragma unroll
    for (int j = 0; j < 4; j++) {
        int i = base + tid * 4 + j;
        if (i < n) {
            float d = g_deg[i];
            g_dinv[i] = (d > 0.f) ? rsqrtf(fmaxf(d, 1e-12f)) : 0.f;
            s += g_cnt[i];
        }
    }
    sh[tid] = s;
    __syncthreads();
    for (int off = 128; off; off >>= 1) {
        if (tid < off) sh[tid] += sh[tid + off];
        __syncthreads();
    }
    if (tid == 0) g_bsum[blockIdx.x] = sh[0];
}

__global__ void k_scanb(int nb) {
    __shared__ int sh[SCAN_NB];
    int tid = threadIdx.x;
    if (tid < nb) sh[tid] = g_bsum[tid];
    __syncthreads();
    if (tid == 0) {
        int run = 0;
        for (int i = 0; i < nb; i++) { int v = sh[i]; sh[i] = run; run += v; }
    }
    __syncthreads();
    if (tid < nb) g_boff[tid] = sh[tid];
}

__global__ void k_fillptr(int n, int total) {
    __shared__ int sh[256];
    int base = blockIdx.x * SCAN_CHUNK;
    int tid = threadIdx.x;
    int c[4];
    int s = 0;
    #pragma unroll
    for (int j = 0; j < 4; j++) {
        int i = base + tid * 4 + j;
        c[j] = (i < n) ? g_cnt[i] : 0;
        s += c[j];
    }
    sh[tid] = s;
    __syncthreads();
    for (int off = 1; off < 256; off <<= 1) {
        int v = (tid >= off) ? sh[tid - off] : 0;
        __syncthreads();
        sh[tid] += v;
        __syncthreads();
    }
    int run = g_boff[blockIdx.x] + ((tid > 0) ? sh[tid - 1] : 0);
    #pragma unroll
    for (int j = 0; j < 4; j++) {
        int i = base + tid * 4 + j;
        if (i < n) { g_colptr[i] = run; run += c[j]; }
    }
    if (blockIdx.x == 0 && tid == 0) g_colptr[n] = total;
}

// no atomics: position = colptr[c] + epos[e]
__global__ void k_scatter(const int* __restrict__ ei, const float* __restrict__ attr, int E, int n) {
    int e = blockIdx.x * blockDim.x + threadIdx.x;
    if (e >= E) return;
    int r = ei[e];
    int c = ei[E + e];
    r = min(max(r, 0), n - 1);
    c = min(max(c, 0), n - 1);
    float nm = g_dinv[r] * attr[e] * g_dinv[c];
    g_csr[g_colptr[c] + g_epos[e]] = make_uint2((unsigned)r, __float_as_uint(nm));
}

// ---------------- conv1 ----------------
// y = A_hat @ x  (single channel)
__global__ void k_prop1(const float* __restrict__ x, int n) {
    int w = (blockIdx.x * blockDim.x + threadIdx.x) >> 5;
    int lane = threadIdx.x & 31;
    if (w >= n) return;
    int beg = g_colptr[w], end = g_colptr[w + 1];
    float acc = 0.f;
    for (int i = beg + lane; i < end; i += 32) {
        uint2 e = g_csr[i];
        acc += x[e.x] * __uint_as_float(e.y);
    }
    #pragma unroll
    for (int o = 16; o; o >>= 1) acc += __shfl_xor_sync(0xffffffffu, acc, o);
    if (lane == 0) g_y[w] = acc;
}

// out1 = relu(y*w_init + x*w_root + b); z = out1 @ W, stored half2 (padded row)
__global__ void k_init1(const float* __restrict__ x,
                        const float* __restrict__ wi, const float* __restrict__ W,
                        const float* __restrict__ wr, const float* __restrict__ b, int n) {
    int idx = blockIdx.x * blockDim.x + threadIdx.x;
    if (idx >= n * 3) return;
    int node = idx / 3, k = idx - node * 3;
    float xv = x[node], yv = g_y[node];
    float o[16];
    #pragma unroll
    for (int h = 0; h < 16; h++) {
        float v = yv * wi[k * 16 + h] + xv * wr[k * 16 + h] + b[k * 16 + h];
        o[h] = fmaxf(v, 0.f);
    }
    __half2* zp = g_z2 + (size_t)node * ZSTRIDE + k * 8;
    #pragma unroll
    for (int j = 0; j < 8; j++) {
        float s0 = 0.f, s1 = 0.f;
        #pragma unroll
        for (int hi = 0; hi < 16; hi++) {
            s0 += o[hi] * W[k * 256 + hi * 16 + 2 * j];
            s1 += o[hi] * W[k * 256 + hi * 16 + 2 * j + 1];
        }
        zp[j] = __floats2half2_rn(s0, s1);
    }
    // zero one pad word per (node,k) so pad region is deterministic
    if (k == 0) {
        float2 zz = make_float2(0.f, 0.f);
        *(float4*)(g_z2 + (size_t)node * ZSTRIDE + 24) = *(float4*)&zz.x,
        *(float4*)(g_z2 + (size_t)node * ZSTRIDE + 28) = *(float4*)&zz.x;
    }
}

// hot kernel: out = relu(A_hat @ z + x*w_root + b)
// warp = 4 edge-slots x 8 chan-slots; one LDG.128 covers 4 edges' state slices
__global__ void k_prop48(const float* __restrict__ x,
                         const float* __restrict__ wr, const float* __restrict__ b, int n) {
    int w = (blockIdx.x * blockDim.x + threadIdx.x) >> 5;
    int lane = threadIdx.x & 31;
    if (w >= n) return;
    int es = lane >> 3;    // edge slot 0..3
    int cs = lane & 7;     // chan slot 0..7 (0..5 carry real channels)
    int beg = g_colptr[w], end = g_colptr[w + 1];
    float acc[8] = {0.f, 0.f, 0.f, 0.f, 0.f, 0.f, 0.f, 0.f};
    for (int i = beg; i < end; i += 4) {
        int src = 0; float nm = 0.f;
        int ie = i + es;
        if (ie < end) { uint2 e = g_csr[ie]; src = (int)e.x; nm = __uint_as_float(e.y); }
        const int4* zp = (const int4*)(g_z2 + (size_t)src * ZSTRIDE) + cs;
        int4 v = *zp;
        float2 f0 = __half22float2(*(__half2*)&v.x);
        float2 f1 = __half22float2(*(__half2*)&v.y);
        float2 f2 = __half22float2(*(__half2*)&v.z);
        float2 f3 = __half22float2(*(__half2*)&v.w);
        acc[0] += f0.x * nm; acc[1] += f0.y * nm;
        acc[2] += f1.x * nm; acc[3] += f1.y * nm;
        acc[4] += f2.x * nm; acc[5] += f2.y * nm;
        acc[6] += f3.x * nm; acc[7] += f3.y * nm;
    }
    #pragma unroll
    for (int c = 0; c < 8; c++) {
        acc[c] += __shfl_xor_sync(0xffffffffu, acc[c], 8);
        acc[c] += __shfl_xor_sync(0xffffffffu, acc[c], 16);
    }
    if (es == 0 && cs < 6) {
        float xv = x[w];
        int c0 = cs * 8;
        float o[8];
        #pragma unroll
        for (int c = 0; c < 8; c++)
            o[c] = fmaxf(acc[c] + xv * wr[c0 + c] + b[c0 + c], 0.f);
        float4* op = (float4*)(g_out + (size_t)w * CH + c0);
        op[0] = make_float4(o[0], o[1], o[2], o[3]);
        op[1] = make_float4(o[4], o[5], o[6], o[7]);
    }
}

// z = out @ W per stack, stored half2 (padded row)
__global__ void k_trans(const float* __restrict__ W, int n) {
    int idx = blockIdx.x * blockDim.x + threadIdx.x;
    if (idx >= n * 3) return;
    int node = idx / 3, k = idx - node * 3;
    const float* op = g_out + (size_t)node * CH + k * 16;
    float o[16];
    #pragma unroll
    for (int h = 0; h < 16; h++) o[h] = op[h];
    __half2* zp = g_z2 + (size_t)node * ZSTRIDE + k * 8;
    #pragma unroll
    for (int j = 0; j < 8; j++) {
        float s0 = 0.f, s1 = 0.f;
        #pragma unroll
        for (int hi = 0; hi < 16; hi++) {
            s0 += o[hi] * W[k * 256 + hi * 16 + 2 * j];
            s1 += o[hi] * W[k * 256 + hi * 16 + 2 * j + 1];
        }
        zp[j] = __floats2half2_rn(s0, s1);
    }
}

// ---------------- batchnorm + conv2 ----------------
__global__ void k_bnstats(int n) {
    int tid = blockIdx.x * blockDim.x + threadIdx.x;
    int stride = gridDim.x * blockDim.x;
    float s = 0.f, q = 0.f;
    for (int base = tid; base < n * 16; base += stride) {
        int node = base >> 4;
        int c = base & 15;
        const float* op = g_out + (size_t)node * CH;
        float h = (op[c] + op[16 + c] + op[32 + c]) * (1.f / 3.f);
        s += h; q += h * h;
    }
    atomicAdd(&g_bnsum[tid & 15], s);
    atomicAdd(&g_bnsq[tid & 15], q);
}

__global__ void k_conv2init(const float* __restrict__ bg, const float* __restrict__ bb,
                            const float* __restrict__ w2i, const float* __restrict__ w2r,
                            const float* __restrict__ b2, int n) {
    int node = blockIdx.x * blockDim.x + threadIdx.x;
    if (node >= n) return;
    const float* op = g_out + (size_t)node * CH;
    float invN = 1.f / (float)n;
    float s0 = 0.f, s1 = 0.f, s2 = 0.f;
    float r0 = b2[0], r1 = b2[1], r2 = b2[2];
    #pragma unroll
    for (int c = 0; c < 16; c++) {
        float h = (op[c] + op[16 + c] + op[32 + c]) * (1.f / 3.f);
        float mu = g_bnsum[c] * invN;
        float var = g_bnsq[c] * invN - mu * mu;
        float hb = (h - mu) * rsqrtf(var + 1e-5f) * bg[c] + bb[c];
        hb = fmaxf(hb, 0.f);
        s0 += hb * w2i[c];
        s1 += hb * w2i[16 + c];
        s2 += hb * w2i[32 + c];
        r0 += hb * w2r[c];
        r1 += hb * w2r[16 + c];
        r2 += hb * w2r[32 + c];
    }
    g_s[0][node] = make_float4(s0, s1, s2, 0.f);
    g_r2[node] = make_float4(r0, r1, r2, 0.f);
}

__global__ void k_prop3(int srcIdx, int useW, int finalOut,
                        const float* __restrict__ w2, float* __restrict__ dout, int n) {
    int w = (blockIdx.x * blockDim.x + threadIdx.x) >> 5;
    int lane = threadIdx.x & 31;
    if (w >= n) return;
    const float4* s = g_s[srcIdx];
    int beg = g_colptr[w], end = g_colptr[w + 1];
    float a0 = 0.f, a1 = 0.f, a2 = 0.f;
    for (int i = beg + lane; i < end; i += 32) {
        uint2 e = g_csr[i];
        float nm = __uint_as_float(e.y);
        float4 v = s[e.x];
        a0 += v.x * nm; a1 += v.y * nm; a2 += v.z * nm;
    }
    #pragma unroll
    for (int o = 16; o; o >>= 1) {
        a0 += __shfl_xor_sync(0xffffffffu, a0, o);
        a1 += __shfl_xor_sync(0xffffffffu, a1, o);
        a2 += __shfl_xor_sync(0xffffffffu, a2, o);
    }
    if (lane == 0) {
        if (useW) { a0 *= w2[0]; a1 *= w2[1]; a2 *= w2[2]; }
        float4 r = g_r2[w];
        a0 += r.x; a1 += r.y; a2 += r.z;
        if (finalOut) {
            float m = (a0 + a1 + a2) * (1.f / 3.f);
            dout[w] = 1.f / (1.f + expf(-m));
        } else {
            g_s[1 - srcIdx][w] = make_float4(a0, a1, a2, 0.f);
        }
    }
}

static inline int cdiv(int a, int b) { return (a + b - 1) / b; }

extern "C" void kernel_launch(void* const* d_in, const int* in_sizes, int n_in,
                              void* d_out, int out_size) {
    const float* x    = (const float*)d_in[0];
    const int*   ei   = (const int*)d_in[1];    // int32 (JAX x64 disabled)
    const float* attr = (const float*)d_in[2];
    const float* w1i  = (const float*)d_in[4];
    const float* w1   = (const float*)d_in[5];
    const float* w1r  = (const float*)d_in[6];
    const float* b1   = (const float*)d_in[7];
    const float* bg   = (const float*)d_in[8];
    const float* bb   = (const float*)d_in[9];
    const float* w2i  = (const float*)d_in[10];
    const float* w2   = (const float*)d_in[11];
    const float* w2r  = (const float*)d_in[12];
    const float* b2   = (const float*)d_in[13];
    float* out = (float*)d_out;

    int N = in_sizes[0];   // 100000
    int E = in_sizes[2];   // 3200000
    int nb = cdiv(N, SCAN_CHUNK);

    // ---- preprocessing: degrees, norms, CSR grouped by target ----
    k_zero<<<cdiv(N, 256), 256>>>(N);
    k_pre<<<cdiv(E, 256), 256>>>(ei, attr, E, N);
    k_dinv_blocksum<<<nb, 256>>>(N);
    k_scanb<<<1, 128>>>(nb);
    k_fillptr<<<nb, 256>>>(N, E);
    k_scatter<<<cdiv(E, 256), 256>>>(ei, attr, E, N);

    // ---- conv1 (K=3, H=16, L=4, relu) ----
    k_prop1<<<cdiv(N * 32, 256), 256>>>(x, N);
    k_init1<<<cdiv(N * 3, 256), 256>>>(x, w1i, w1, w1r, b1, N);
    for (int t = 1; t <= 3; t++) {
        k_prop48<<<cdiv(N, 8), 256>>>(x, w1r, b1, N);
        if (t < 3) k_trans<<<cdiv(N * 3, 256), 256>>>(w1, N);
    }

    // ---- batchnorm + relu, conv2 init ----
    k_bnstats<<<232, 256>>>(N);
    k_conv2init<<<cdiv(N, 256), 256>>>(bg, bb, w2i, w2r, b2, N);

    // ---- conv2 (K=3, C=1, L=4, no act) + mean + sigmoid ----
    k_prop3<<<cdiv(N, 8), 256>>>(0, 0, 0, w2, out, N);
    k_prop3<<<cdiv(N, 8), 256>>>(1, 1, 0, w2, out, N);
    k_prop3<<<cdiv(N, 8), 256>>>(0, 1, 0, w2, out, N);
    k_prop3<<<cdiv(N, 8), 256>>>(1, 1, 1, w2, out, N);
}

// round 7
// speedup vs baseline: 1.4952x; 1.0839x over previous
#include <cuda_runtime.h>
#include <cuda_fp16.h>
#include <math.h>

// Problem constants (fixed by the dataset)
#define N_MAX 100000
#define E_MAX 3200000
#define CH 48            // K*H = 3*16
#define ZSTRIDE 32       // half2 words per node (24 used + 8 pad = 128B line)
#define SCAN_CHUNK 1024
#define SCAN_NB ((N_MAX + SCAN_CHUNK - 1) / SCAN_CHUNK)   // 98

// ---------------- persistent device scratch ----------------
__device__ float   g_deg[N_MAX];
__device__ float   g_dinv[N_MAX];
__device__ int     g_cnt[N_MAX];
__device__ int     g_colptr[N_MAX + 1];
__device__ int     g_epos[E_MAX];        // per-edge rank within its target bucket
__device__ int     g_bsum[SCAN_NB];
__device__ int     g_boff[SCAN_NB];
__device__ uint2   g_csr[E_MAX];         // {src, norm-bits} grouped by target
__device__ float   g_y[N_MAX];           // y = A_hat @ x
__device__ __align__(16) __half2 g_z2[(size_t)N_MAX * ZSTRIDE]; // padded state
__device__ float   g_out[(size_t)N_MAX * CH]; // post-epilogue out (fp32)
__device__ float4  g_s[2][N_MAX];        // conv2 state ping/pong
__device__ float4  g_r2[N_MAX];          // conv2 root+bias per stack
__device__ float   g_bnsum[16];
__device__ float   g_bnsq[16];

// ---------------- preprocessing ----------------
__global__ void k_zero(int n) {
    int i = blockIdx.x * blockDim.x + threadIdx.x;
    if (i < n) { g_deg[i] = 0.f; g_cnt[i] = 0; }
    if (i < 16) { g_bnsum[i] = 0.f; g_bnsq[i] = 0.f; }
}

// edge_index is int32. Record each edge's bucket rank from the cnt atomic.
__global__ void k_pre(const int* __restrict__ ei, const float* __restrict__ attr, int E, int n) {
    int e = blockIdx.x * blockDim.x + threadIdx.x;
    if (e >= E) return;
    int c = ei[E + e];
    c = min(max(c, 0), n - 1);
    atomicAdd(&g_deg[c], attr[e]);
    g_epos[e] = atomicAdd(&g_cnt[c], 1);
}

// fused: dinv for this block's 1024 nodes + block sum of cnt
__global__ void k_dinv_blocksum(int n) {
    __shared__ int sh[256];
    int base = blockIdx.x * SCAN_CHUNK;
    int tid = threadIdx.x;
    int s = 0;
    #pragma unroll
    for (int j = 0; j < 4; j++) {
        int i = base + tid * 4 + j;
        if (i < n) {
            float d = g_deg[i];
            g_dinv[i] = (d > 0.f) ? rsqrtf(fmaxf(d, 1e-12f)) : 0.f;
            s += g_cnt[i];
        }
    }
    sh[tid] = s;
    __syncthreads();
    for (int off = 128; off; off >>= 1) {
        if (tid < off) sh[tid] += sh[tid + off];
        __syncthreads();
    }
    if (tid == 0) g_bsum[blockIdx.x] = sh[0];
}

__global__ void k_scanb(int nb) {
    __shared__ int sh[SCAN_NB];
    int tid = threadIdx.x;
    if (tid < nb) sh[tid] = g_bsum[tid];
    __syncthreads();
    if (tid == 0) {
        int run = 0;
        for (int i = 0; i < nb; i++) { int v = sh[i]; sh[i] = run; run += v; }
    }
    __syncthreads();
    if (tid < nb) g_boff[tid] = sh[tid];
}

__global__ void k_fillptr(int n, int total) {
    __shared__ int sh[256];
    int base = blockIdx.x * SCAN_CHUNK;
    int tid = threadIdx.x;
    int c[4];
    int s = 0;
    #pragma unroll
    for (int j = 0; j < 4; j++) {
        int i = base + tid * 4 + j;
        c[j] = (i < n) ? g_cnt[i] : 0;
        s += c[j];
    }
    sh[tid] = s;
    __syncthreads();
    for (int off = 1; off < 256; off <<= 1) {
        int v = (tid >= off) ? sh[tid - off] : 0;
        __syncthreads();
        sh[tid] += v;
        __syncthreads();
    }
    int run = g_boff[blockIdx.x] + ((tid > 0) ? sh[tid - 1] : 0);
    #pragma unroll
    for (int j = 0; j < 4; j++) {
        int i = base + tid * 4 + j;
        if (i < n) { g_colptr[i] = run; run += c[j]; }
    }
    if (blockIdx.x == 0 && tid == 0) g_colptr[n] = total;
}

// no atomics: position = colptr[c] + epos[e]
__global__ void k_scatter(const int* __restrict__ ei, const float* __restrict__ attr, int E, int n) {
    int e = blockIdx.x * blockDim.x + threadIdx.x;
    if (e >= E) return;
    int r = ei[e];
    int c = ei[E + e];
    r = min(max(r, 0), n - 1);
    c = min(max(c, 0), n - 1);
    float nm = g_dinv[r] * attr[e] * g_dinv[c];
    g_csr[g_colptr[c] + g_epos[e]] = make_uint2((unsigned)r, __float_as_uint(nm));
}

// ---------------- conv1 ----------------
// y = A_hat @ x  (single channel)
__global__ void k_prop1(const float* __restrict__ x, int n) {
    int w = (blockIdx.x * blockDim.x + threadIdx.x) >> 5;
    int lane = threadIdx.x & 31;
    if (w >= n) return;
    int beg = g_colptr[w], end = g_colptr[w + 1];
    float acc = 0.f;
    for (int i = beg + lane; i < end; i += 32) {
        uint2 e = g_csr[i];
        acc += x[e.x] * __uint_as_float(e.y);
    }
    #pragma unroll
    for (int o = 16; o; o >>= 1) acc += __shfl_xor_sync(0xffffffffu, acc, o);
    if (lane == 0) g_y[w] = acc;
}

// out1 = relu(y*w_init + x*w_root + b); z = out1 @ W, stored half2 (padded row)
__global__ void k_init1(const float* __restrict__ x,
                        const float* __restrict__ wi, const float* __restrict__ W,
                        const float* __restrict__ wr, const float* __restrict__ b, int n) {
    int idx = blockIdx.x * blockDim.x + threadIdx.x;
    if (idx >= n * 3) return;
    int node = idx / 3, k = idx - node * 3;
    float xv = x[node], yv = g_y[node];
    float o[16];
    #pragma unroll
    for (int h = 0; h < 16; h++) {
        float v = yv * wi[k * 16 + h] + xv * wr[k * 16 + h] + b[k * 16 + h];
        o[h] = fmaxf(v, 0.f);
    }
    __half2* zp = g_z2 + (size_t)node * ZSTRIDE + k * 8;
    #pragma unroll
    for (int j = 0; j < 8; j++) {
        float s0 = 0.f, s1 = 0.f;
        #pragma unroll
        for (int hi = 0; hi < 16; hi++) {
            s0 += o[hi] * W[k * 256 + hi * 16 + 2 * j];
            s1 += o[hi] * W[k * 256 + hi * 16 + 2 * j + 1];
        }
        zp[j] = __floats2half2_rn(s0, s1);
    }
    // zero pad words so the pad region is deterministic
    if (k == 0) {
        int4 zz = make_int4(0, 0, 0, 0);
        *(int4*)(g_z2 + (size_t)node * ZSTRIDE + 24) = zz;
        *(int4*)(g_z2 + (size_t)node * ZSTRIDE + 28) = zz;
    }
}

// hot kernel: out = relu(A_hat @ z + x*w_root + b); optionally fused z' = out @ W
// warp = 4 edge-slots x 8 chan-slots; 8-edge unroll (two int4 gathers in flight)
__global__ void k_prop48(const float* __restrict__ x,
                         const float* __restrict__ wr, const float* __restrict__ b,
                         const float* __restrict__ W, int doTrans, int n) {
    __shared__ float s_out[8][CH];   // per-warp out vector
    __shared__ float s_W[768];       // 3 stacks x 16 x 16
    int tid = threadIdx.x;
    if (doTrans) {
        for (int i = tid; i < 768; i += 256) s_W[i] = W[i];
    }
    __syncthreads();

    int warpid = tid >> 5;
    int w = blockIdx.x * 8 + warpid;
    if (w >= n) return;
    int lane = tid & 31;
    int es = lane >> 3;    // edge slot 0..3
    int cs = lane & 7;     // chan slot 0..7 (0..5 carry real channels)
    int beg = g_colptr[w], end = g_colptr[w + 1];
    float accA[8] = {0.f, 0.f, 0.f, 0.f, 0.f, 0.f, 0.f, 0.f};
    float accB[8] = {0.f, 0.f, 0.f, 0.f, 0.f, 0.f, 0.f, 0.f};
    for (int i = beg; i < end; i += 8) {
        int ie0 = i + es, ie1 = i + es + 4;
        int s0 = 0, s1 = 0; float n0 = 0.f, n1 = 0.f;
        if (ie0 < end) { uint2 e = g_csr[ie0]; s0 = (int)e.x; n0 = __uint_as_float(e.y); }
        if (ie1 < end) { uint2 e = g_csr[ie1]; s1 = (int)e.x; n1 = __uint_as_float(e.y); }
        int4 v0 = *((const int4*)(g_z2 + (size_t)s0 * ZSTRIDE) + cs);
        int4 v1 = *((const int4*)(g_z2 + (size_t)s1 * ZSTRIDE) + cs);
        {
            float2 f0 = __half22float2(*(__half2*)&v0.x);
            float2 f1 = __half22float2(*(__half2*)&v0.y);
            float2 f2 = __half22float2(*(__half2*)&v0.z);
            float2 f3 = __half22float2(*(__half2*)&v0.w);
            accA[0] += f0.x * n0; accA[1] += f0.y * n0;
            accA[2] += f1.x * n0; accA[3] += f1.y * n0;
            accA[4] += f2.x * n0; accA[5] += f2.y * n0;
            accA[6] += f3.x * n0; accA[7] += f3.y * n0;
        }
        {
            float2 f0 = __half22float2(*(__half2*)&v1.x);
            float2 f1 = __half22float2(*(__half2*)&v1.y);
            float2 f2 = __half22float2(*(__half2*)&v1.z);
            float2 f3 = __half22float2(*(__half2*)&v1.w);
            accB[0] += f0.x * n1; accB[1] += f0.y * n1;
            accB[2] += f1.x * n1; accB[3] += f1.y * n1;
            accB[4] += f2.x * n1; accB[5] += f2.y * n1;
            accB[6] += f3.x * n1; accB[7] += f3.y * n1;
        }
    }
    #pragma unroll
    for (int c = 0; c < 8; c++) {
        float a = accA[c] + accB[c];
        a += __shfl_xor_sync(0xffffffffu, a, 8);
        a += __shfl_xor_sync(0xffffffffu, a, 16);
        accA[c] = a;
    }
    if (es == 0 && cs < 6) {
        float xv = x[w];
        int c0 = cs * 8;
        float o[8];
        #pragma unroll
        for (int c = 0; c < 8; c++) {
            o[c] = fmaxf(accA[c] + xv * wr[c0 + c] + b[c0 + c], 0.f);
            s_out[warpid][c0 + c] = o[c];
        }
        float4* op = (float4*)(g_out + (size_t)w * CH + c0);
        op[0] = make_float4(o[0], o[1], o[2], o[3]);
        op[1] = make_float4(o[4], o[5], o[6], o[7]);
    }
    if (doTrans) {
        __syncwarp();
        // lanes 0..23: z'[k][2j],[2j+1]; lanes 24..31 zero the pad word
        if (lane < 24) {
            int k = lane >> 3;          // stack 0..2
            int j = lane & 7;           // half2 word within stack
            const float* ov = s_out[warpid] + k * 16;
            const float* Wk = s_W + k * 256;
            float z0 = 0.f, z1 = 0.f;
            #pragma unroll
            for (int hi = 0; hi < 16; hi++) {
                z0 += ov[hi] * Wk[hi * 16 + 2 * j];
                z1 += ov[hi] * Wk[hi * 16 + 2 * j + 1];
            }
            g_z2[(size_t)w * ZSTRIDE + k * 8 + j] = __floats2half2_rn(z0, z1);
        } else {
            g_z2[(size_t)w * ZSTRIDE + lane] = __floats2half2_rn(0.f, 0.f);
        }
    }
}

// ---------------- batchnorm + conv2 ----------------
__global__ void k_bnstats(int n) {
    int tid = blockIdx.x * blockDim.x + threadIdx.x;
    int stride = gridDim.x * blockDim.x;
    float s = 0.f, q = 0.f;
    for (int base = tid; base < n * 16; base += stride) {
        int node = base >> 4;
        int c = base & 15;
        const float* op = g_out + (size_t)node * CH;
        float h = (op[c] + op[16 + c] + op[32 + c]) * (1.f / 3.f);
        s += h; q += h * h;
    }
    atomicAdd(&g_bnsum[tid & 15], s);
    atomicAdd(&g_bnsq[tid & 15], q);
}

__global__ void k_conv2init(const float* __restrict__ bg, const float* __restrict__ bb,
                            const float* __restrict__ w2i, const float* __restrict__ w2r,
                            const float* __restrict__ b2, int n) {
    int node = blockIdx.x * blockDim.x + threadIdx.x;
    if (node >= n) return;
    const float* op = g_out + (size_t)node * CH;
    float invN = 1.f / (float)n;
    float s0 = 0.f, s1 = 0.f, s2 = 0.f;
    float r0 = b2[0], r1 = b2[1], r2 = b2[2];
    #pragma unroll
    for (int c = 0; c < 16; c++) {
        float h = (op[c] + op[16 + c] + op[32 + c]) * (1.f / 3.f);
        float mu = g_bnsum[c] * invN;
        float var = g_bnsq[c] * invN - mu * mu;
        float hb = (h - mu) * rsqrtf(var + 1e-5f) * bg[c] + bb[c];
        hb = fmaxf(hb, 0.f);
        s0 += hb * w2i[c];
        s1 += hb * w2i[16 + c];
        s2 += hb * w2i[32 + c];
        r0 += hb * w2r[c];
        r1 += hb * w2r[16 + c];
        r2 += hb * w2r[32 + c];
    }
    g_s[0][node] = make_float4(s0, s1, s2, 0.f);
    g_r2[node] = make_float4(r0, r1, r2, 0.f);
}

__global__ void k_prop3(int srcIdx, int useW, int finalOut,
                        const float* __restrict__ w2, float* __restrict__ dout, int n) {
    int w = (blockIdx.x * blockDim.x + threadIdx.x) >> 5;
    int lane = threadIdx.x & 31;
    if (w >= n) return;
    const float4* s = g_s[srcIdx];
    int beg = g_colptr[w], end = g_colptr[w + 1];
    float a0 = 0.f, a1 = 0.f, a2 = 0.f;
    for (int i = beg + lane; i < end; i += 32) {
        uint2 e = g_csr[i];
        float nm = __uint_as_float(e.y);
        float4 v = s[e.x];
        a0 += v.x * nm; a1 += v.y * nm; a2 += v.z * nm;
    }
    #pragma unroll
    for (int o = 16; o; o >>= 1) {
        a0 += __shfl_xor_sync(0xffffffffu, a0, o);
        a1 += __shfl_xor_sync(0xffffffffu, a1, o);
        a2 += __shfl_xor_sync(0xffffffffu, a2, o);
    }
    if (lane == 0) {
        if (useW) { a0 *= w2[0]; a1 *= w2[1]; a2 *= w2[2]; }
        float4 r = g_r2[w];
        a0 += r.x; a1 += r.y; a2 += r.z;
        if (finalOut) {
            float m = (a0 + a1 + a2) * (1.f / 3.f);
            dout[w] = 1.f / (1.f + expf(-m));
        } else {
            g_s[1 - srcIdx][w] = make_float4(a0, a1, a2, 0.f);
        }
    }
}

static inline int cdiv(int a, int b) { return (a + b - 1) / b; }

extern "C" void kernel_launch(void* const* d_in, const int* in_sizes, int n_in,
                              void* d_out, int out_size) {
    const float* x    = (const float*)d_in[0];
    const int*   ei   = (const int*)d_in[1];    // int32 (JAX x64 disabled)
    const float* attr = (const float*)d_in[2];
    const float* w1i  = (const float*)d_in[4];
    const float* w1   = (const float*)d_in[5];
    const float* w1r  = (const float*)d_in[6];
    const float* b1   = (const float*)d_in[7];
    const float* bg   = (const float*)d_in[8];
    const float* bb   = (const float*)d_in[9];
    const float* w2i  = (const float*)d_in[10];
    const float* w2   = (const float*)d_in[11];
    const float* w2r  = (const float*)d_in[12];
    const float* b2   = (const float*)d_in[13];
    float* out = (float*)d_out;

    int N = in_sizes[0];   // 100000
    int E = in_sizes[2];   // 3200000
    int nb = cdiv(N, SCAN_CHUNK);

    // ---- preprocessing: degrees, norms, CSR grouped by target ----
    k_zero<<<cdiv(N, 256), 256>>>(N);
    k_pre<<<cdiv(E, 256), 256>>>(ei, attr, E, N);
    k_dinv_blocksum<<<nb, 256>>>(N);
    k_scanb<<<1, 128>>>(nb);
    k_fillptr<<<nb, 256>>>(N, E);
    k_scatter<<<cdiv(E, 256), 256>>>(ei, attr, E, N);

    // ---- conv1 (K=3, H=16, L=4, relu); trans fused into prop48 ----
    k_prop1<<<cdiv(N * 32, 256), 256>>>(x, N);
    k_init1<<<cdiv(N * 3, 256), 256>>>(x, w1i, w1, w1r, b1, N);
    k_prop48<<<cdiv(N, 8), 256>>>(x, w1r, b1, w1, 1, N);
    k_prop48<<<cdiv(N, 8), 256>>>(x, w1r, b1, w1, 1, N);
    k_prop48<<<cdiv(N, 8), 256>>>(x, w1r, b1, w1, 0, N);

    // ---- batchnorm + relu, conv2 init ----
    k_bnstats<<<232, 256>>>(N);
    k_conv2init<<<cdiv(N, 256), 256>>>(bg, bb, w2i, w2r, b2, N);

    // ---- conv2 (K=3, C=1, L=4, no act) + mean + sigmoid ----
    k_prop3<<<cdiv(N, 8), 256>>>(0, 0, 0, w2, out, N);
    k_prop3<<<cdiv(N, 8), 256>>>(1, 1, 0, w2, out, N);
    k_prop3<<<cdiv(N, 8), 256>>>(0, 1, 0, w2, out, N);
    k_prop3<<<cdiv(N, 8), 256>>>(1, 1, 1, w2, out, N);
}

// round 8
// speedup vs baseline: 1.5878x; 1.0619x over previous
#include <cuda_runtime.h>
#include <cuda_fp16.h>
#include <math.h>

// Problem constants (fixed by the dataset)
#define N_MAX 100000
#define E_MAX 3200000
#define CH 48            // K*H = 3*16
#define ZSTRIDE 32       // half2 words per node (24 used + 8 pad = 128B line)
#define SCAN_CHUNK 1024
#define SCAN_NB ((N_MAX + SCAN_CHUNK - 1) / SCAN_CHUNK)   // 98

// ---------------- persistent device scratch ----------------
__device__ float   g_deg[N_MAX];
__device__ float2  g_xd[N_MAX];          // packed {x, dinv}
__device__ int     g_cnt[N_MAX];
__device__ int     g_colptr[N_MAX + 1];
__device__ int     g_epos[E_MAX];        // per-edge rank within its target bucket
__device__ int     g_bsum[SCAN_NB];
__device__ uint2   g_csr[E_MAX];         // {src, attr-bits} then {src, norm-bits}
__device__ __align__(16) __half2 g_z2[(size_t)N_MAX * ZSTRIDE]; // padded state
__device__ float   g_out[(size_t)N_MAX * CH]; // post-epilogue out (fp32)
__device__ float4  g_s[2][N_MAX];        // conv2 state ping/pong
__device__ float4  g_r2[N_MAX];          // conv2 root+bias per stack
__device__ float   g_bnsum[16];
__device__ float   g_bnsq[16];

// ---------------- preprocessing ----------------
__global__ void k_zero(int n) {
    int i = blockIdx.x * blockDim.x + threadIdx.x;
    if (i < n) { g_deg[i] = 0.f; g_cnt[i] = 0; }
    if (i < 16) { g_bnsum[i] = 0.f; g_bnsq[i] = 0.f; }
}

// edge_index is int32. Record each edge's bucket rank from the cnt atomic.
__global__ void k_pre(const int* __restrict__ ei, const float* __restrict__ attr, int E, int n) {
    int e = blockIdx.x * blockDim.x + threadIdx.x;
    if (e >= E) return;
    int c = ei[E + e];
    c = min(max(c, 0), n - 1);
    atomicAdd(&g_deg[c], attr[e]);
    g_epos[e] = atomicAdd(&g_cnt[c], 1);
}

// fused: {x, dinv} pack for this block's 1024 nodes + block sum of cnt
__global__ void k_dinv_blocksum(const float* __restrict__ x, int n) {
    __shared__ int sh[256];
    int base = blockIdx.x * SCAN_CHUNK;
    int tid = threadIdx.x;
    int s = 0;
    #pragma unroll
    for (int j = 0; j < 4; j++) {
        int i = base + tid * 4 + j;
        if (i < n) {
            float d = g_deg[i];
            float dv = (d > 0.f) ? rsqrtf(fmaxf(d, 1e-12f)) : 0.f;
            g_xd[i] = make_float2(x[i], dv);
            s += g_cnt[i];
        }
    }
    sh[tid] = s;
    __syncthreads();
    for (int off = 128; off; off >>= 1) {
        if (tid < off) sh[tid] += sh[tid + off];
        __syncthreads();
    }
    if (tid == 0) g_bsum[blockIdx.x] = sh[0];
}

// fillptr with inline prefix of block sums (scanb fused away)
__global__ void k_fillptr(int n, int total) {
    __shared__ int sh[256];
    __shared__ int s_boff;
    int base = blockIdx.x * SCAN_CHUNK;
    int tid = threadIdx.x;
    if (tid < 32) {
        int acc = 0;
        for (int i = tid; i < blockIdx.x; i += 32) acc += g_bsum[i];
        #pragma unroll
        for (int o = 16; o; o >>= 1) acc += __shfl_xor_sync(0xffffffffu, acc, o);
        if (tid == 0) s_boff = acc;
    }
    int c[4];
    int s = 0;
    #pragma unroll
    for (int j = 0; j < 4; j++) {
        int i = base + tid * 4 + j;
        c[j] = (i < n) ? g_cnt[i] : 0;
        s += c[j];
    }
    sh[tid] = s;
    __syncthreads();
    for (int off = 1; off < 256; off <<= 1) {
        int v = (tid >= off) ? sh[tid - off] : 0;
        __syncthreads();
        sh[tid] += v;
        __syncthreads();
    }
    int run = s_boff + ((tid > 0) ? sh[tid - 1] : 0);
    #pragma unroll
    for (int j = 0; j < 4; j++) {
        int i = base + tid * 4 + j;
        if (i < n) { g_colptr[i] = run; run += c[j]; }
    }
    if (blockIdx.x == 0 && tid == 0) g_colptr[n] = total;
}

// scatter {src, attr}: no dinv gathers; norm computed later in k_prop1i
__global__ void k_scatter(const int* __restrict__ ei, const float* __restrict__ attr, int E, int n) {
    int e = blockIdx.x * blockDim.x + threadIdx.x;
    if (e >= E) return;
    int r = ei[e];
    int c = ei[E + e];
    r = min(max(r, 0), n - 1);
    c = min(max(c, 0), n - 1);
    g_csr[g_colptr[c] + g_epos[e]] = make_uint2((unsigned)r, __float_as_uint(attr[e]));
}

// ---------------- conv1 layer 0, fused ----------------
// per node: finalize norms in CSR, y = A_hat x, out1 = relu(y*wi + x*wr + b), z = out1 @ W
__global__ void k_prop1i(const float* __restrict__ wi, const float* __restrict__ W,
                         const float* __restrict__ wr, const float* __restrict__ b, int n) {
    __shared__ float s_wi[48], s_wr[48], s_b[48], s_W[768];
    int tid = threadIdx.x;
    if (tid < 48) { s_wi[tid] = wi[tid]; s_wr[tid] = wr[tid]; s_b[tid] = b[tid]; }
    for (int i = tid; i < 768; i += 256) s_W[i] = W[i];
    __syncthreads();

    int w = blockIdx.x * 8 + (tid >> 5);
    if (w >= n) return;
    int lane = tid & 31;
    float2 xdw = g_xd[w];
    float dinv_w = xdw.y, xv = xdw.x;
    int beg = g_colptr[w], end = g_colptr[w + 1];
    float acc = 0.f;
    for (int i = beg + lane; i < end; i += 32) {
        uint2 e = g_csr[i];
        float2 xd = g_xd[e.x];
        float nm = xd.y * __uint_as_float(e.y) * dinv_w;
        g_csr[i] = make_uint2(e.x, __float_as_uint(nm));
        acc += xd.x * nm;
    }
    #pragma unroll
    for (int o = 16; o; o >>= 1) acc += __shfl_xor_sync(0xffffffffu, acc, o);
    float yv = acc;   // all lanes have y

    if (lane < 24) {
        int k = lane >> 3;      // stack
        int j = lane & 7;       // half2 word within stack
        const float* wik = s_wi + k * 16;
        const float* wrk = s_wr + k * 16;
        const float* bk  = s_b  + k * 16;
        const float* Wk  = s_W  + k * 256;
        float z0 = 0.f, z1 = 0.f;
        #pragma unroll
        for (int hi = 0; hi < 16; hi++) {
            float o = fmaxf(yv * wik[hi] + xv * wrk[hi] + bk[hi], 0.f);
            z0 += o * Wk[hi * 16 + 2 * j];
            z1 += o * Wk[hi * 16 + 2 * j + 1];
        }
        g_z2[(size_t)w * ZSTRIDE + k * 8 + j] = __floats2half2_rn(z0, z1);
    } else {
        g_z2[(size_t)w * ZSTRIDE + lane] = __floats2half2_rn(0.f, 0.f);
    }
}

// hot kernel: out = relu(A_hat @ z + x*w_root + b); optionally fused z' = out @ W
// warp = 4 edge-slots x 8 chan-slots; 8-edge unroll + CSR software pipeline
__global__ void k_prop48(const float* __restrict__ wr, const float* __restrict__ b,
                         const float* __restrict__ W, int doTrans, int n) {
    __shared__ float s_out[8][CH];   // per-warp out vector
    __shared__ float s_W[768];       // 3 stacks x 16 x 16
    int tid = threadIdx.x;
    if (doTrans) {
        for (int i = tid; i < 768; i += 256) s_W[i] = W[i];
    }
    __syncthreads();

    int warpid = tid >> 5;
    int w = blockIdx.x * 8 + warpid;
    if (w >= n) return;
    int lane = tid & 31;
    int es = lane >> 3;    // edge slot 0..3
    int cs = lane & 7;     // chan slot 0..7 (0..5 carry real channels)
    int beg = g_colptr[w], end = g_colptr[w + 1];
    float accA[8] = {0.f, 0.f, 0.f, 0.f, 0.f, 0.f, 0.f, 0.f};
    float accB[8] = {0.f, 0.f, 0.f, 0.f, 0.f, 0.f, 0.f, 0.f};

    if (beg < end) {
        int last = end - 1;
        uint2 e0 = g_csr[min(beg + es, last)];
        uint2 e1 = g_csr[min(beg + es + 4, last)];
        bool ok0 = beg + es < end, ok1 = beg + es + 4 < end;
        for (int i = beg; i < end; i += 8) {
            // issue z gathers for current records (deps already in regs)
            int4 v0 = *((const int4*)(g_z2 + (size_t)e0.x * ZSTRIDE) + cs);
            int4 v1 = *((const int4*)(g_z2 + (size_t)e1.x * ZSTRIDE) + cs);
            float n0 = ok0 ? __uint_as_float(e0.y) : 0.f;
            float n1 = ok1 ? __uint_as_float(e1.y) : 0.f;
            // prefetch next iteration's CSR records (independent)
            int ni = i + 8;
            if (ni < end) {
                e0 = g_csr[min(ni + es, last)];
                e1 = g_csr[min(ni + es + 4, last)];
                ok0 = ni + es < end; ok1 = ni + es + 4 < end;
            }
            {
                float2 f0 = __half22float2(*(__half2*)&v0.x);
                float2 f1 = __half22float2(*(__half2*)&v0.y);
                float2 f2 = __half22float2(*(__half2*)&v0.z);
                float2 f3 = __half22float2(*(__half2*)&v0.w);
                accA[0] += f0.x * n0; accA[1] += f0.y * n0;
                accA[2] += f1.x * n0; accA[3] += f1.y * n0;
                accA[4] += f2.x * n0; accA[5] += f2.y * n0;
                accA[6] += f3.x * n0; accA[7] += f3.y * n0;
            }
            {
                float2 f0 = __half22float2(*(__half2*)&v1.x);
                float2 f1 = __half22float2(*(__half2*)&v1.y);
                float2 f2 = __half22float2(*(__half2*)&v1.z);
                float2 f3 = __half22float2(*(__half2*)&v1.w);
                accB[0] += f0.x * n1; accB[1] += f0.y * n1;
                accB[2] += f1.x * n1; accB[3] += f1.y * n1;
                accB[4] += f2.x * n1; accB[5] += f2.y * n1;
                accB[6] += f3.x * n1; accB[7] += f3.y * n1;
            }
        }
    }
    #pragma unroll
    for (int c = 0; c < 8; c++) {
        float a = accA[c] + accB[c];
        a += __shfl_xor_sync(0xffffffffu, a, 8);
        a += __shfl_xor_sync(0xffffffffu, a, 16);
        accA[c] = a;
    }
    if (es == 0 && cs < 6) {
        float xv = g_xd[w].x;
        int c0 = cs * 8;
        float o[8];
        #pragma unroll
        for (int c = 0; c < 8; c++) {
            o[c] = fmaxf(accA[c] + xv * wr[c0 + c] + b[c0 + c], 0.f);
            s_out[warpid][c0 + c] = o[c];
        }
        float4* op = (float4*)(g_out + (size_t)w * CH + c0);
        op[0] = make_float4(o[0], o[1], o[2], o[3]);
        op[1] = make_float4(o[4], o[5], o[6], o[7]);
    }
    if (doTrans) {
        __syncwarp();
        if (lane < 24) {
            int k = lane >> 3;
            int j = lane & 7;
            const float* ov = s_out[warpid] + k * 16;
            const float* Wk = s_W + k * 256;
            float z0 = 0.f, z1 = 0.f;
            #pragma unroll
            for (int hi = 0; hi < 16; hi++) {
                z0 += ov[hi] * Wk[hi * 16 + 2 * j];
                z1 += ov[hi] * Wk[hi * 16 + 2 * j + 1];
            }
            g_z2[(size_t)w * ZSTRIDE + k * 8 + j] = __floats2half2_rn(z0, z1);
        } else {
            g_z2[(size_t)w * ZSTRIDE + lane] = __floats2half2_rn(0.f, 0.f);
        }
    }
}

// ---------------- batchnorm + conv2 ----------------
__global__ void k_bnstats(int n) {
    int tid = blockIdx.x * blockDim.x + threadIdx.x;
    int stride = gridDim.x * blockDim.x;
    float s = 0.f, q = 0.f;
    for (int base = tid; base < n * 16; base += stride) {
        int node = base >> 4;
        int c = base & 15;
        const float* op = g_out + (size_t)node * CH;
        float h = (op[c] + op[16 + c] + op[32 + c]) * (1.f / 3.f);
        s += h; q += h * h;
    }
    atomicAdd(&g_bnsum[tid & 15], s);
    atomicAdd(&g_bnsq[tid & 15], q);
}

__global__ void k_conv2init(const float* __restrict__ bg, const float* __restrict__ bb,
                            const float* __restrict__ w2i, const float* __restrict__ w2r,
                            const float* __restrict__ b2, int n) {
    int node = blockIdx.x * blockDim.x + threadIdx.x;
    if (node >= n) return;
    const float* op = g_out + (size_t)node * CH;
    float invN = 1.f / (float)n;
    float s0 = 0.f, s1 = 0.f, s2 = 0.f;
    float r0 = b2[0], r1 = b2[1], r2 = b2[2];
    #pragma unroll
    for (int c = 0; c < 16; c++) {
        float h = (op[c] + op[16 + c] + op[32 + c]) * (1.f / 3.f);
        float mu = g_bnsum[c] * invN;
        float var = g_bnsq[c] * invN - mu * mu;
        float hb = (h - mu) * rsqrtf(var + 1e-5f) * bg[c] + bb[c];
        hb = fmaxf(hb, 0.f);
        s0 += hb * w2i[c];
        s1 += hb * w2i[16 + c];
        s2 += hb * w2i[32 + c];
        r0 += hb * w2r[c];
        r1 += hb * w2r[16 + c];
        r2 += hb * w2r[32 + c];
    }
    g_s[0][node] = make_float4(s0, s1, s2, 0.f);
    g_r2[node] = make_float4(r0, r1, r2, 0.f);
}

__global__ void k_prop3(int srcIdx, int useW, int finalOut,
                        const float* __restrict__ w2, float* __restrict__ dout, int n) {
    int w = (blockIdx.x * blockDim.x + threadIdx.x) >> 5;
    int lane = threadIdx.x & 31;
    if (w >= n) return;
    const float4* s = g_s[srcIdx];
    int beg = g_colptr[w], end = g_colptr[w + 1];
    float a0 = 0.f, a1 = 0.f, a2 = 0.f;
    for (int i = beg + lane; i < end; i += 32) {
        uint2 e = g_csr[i];
        float nm = __uint_as_float(e.y);
        float4 v = s[e.x];
        a0 += v.x * nm; a1 += v.y * nm; a2 += v.z * nm;
    }
    #pragma unroll
    for (int o = 16; o; o >>= 1) {
        a0 += __shfl_xor_sync(0xffffffffu, a0, o);
        a1 += __shfl_xor_sync(0xffffffffu, a1, o);
        a2 += __shfl_xor_sync(0xffffffffu, a2, o);
    }
    if (lane == 0) {
        if (useW) { a0 *= w2[0]; a1 *= w2[1]; a2 *= w2[2]; }
        float4 r = g_r2[w];
        a0 += r.x; a1 += r.y; a2 += r.z;
        if (finalOut) {
            float m = (a0 + a1 + a2) * (1.f / 3.f);
            dout[w] = 1.f / (1.f + expf(-m));
        } else {
            g_s[1 - srcIdx][w] = make_float4(a0, a1, a2, 0.f);
        }
    }
}

static inline int cdiv(int a, int b) { return (a + b - 1) / b; }

extern "C" void kernel_launch(void* const* d_in, const int* in_sizes, int n_in,
                              void* d_out, int out_size) {
    const float* x    = (const float*)d_in[0];
    const int*   ei   = (const int*)d_in[1];    // int32 (JAX x64 disabled)
    const float* attr = (const float*)d_in[2];
    const float* w1i  = (const float*)d_in[4];
    const float* w1   = (const float*)d_in[5];
    const float* w1r  = (const float*)d_in[6];
    const float* b1   = (const float*)d_in[7];
    const float* bg   = (const float*)d_in[8];
    const float* bb   = (const float*)d_in[9];
    const float* w2i  = (const float*)d_in[10];
    const float* w2   = (const float*)d_in[11];
    const float* w2r  = (const float*)d_in[12];
    const float* b2   = (const float*)d_in[13];
    float* out = (float*)d_out;

    int N = in_sizes[0];   // 100000
    int E = in_sizes[2];   // 3200000
    int nb = cdiv(N, SCAN_CHUNK);

    // ---- preprocessing: degrees, CSR grouped by target (attr payload) ----
    k_zero<<<cdiv(N, 256), 256>>>(N);
    k_pre<<<cdiv(E, 256), 256>>>(ei, attr, E, N);
    k_dinv_blocksum<<<nb, 256>>>(x, N);
    k_fillptr<<<nb, 256>>>(N, E);
    k_scatter<<<cdiv(E, 256), 256>>>(ei, attr, E, N);

    // ---- conv1 (K=3, H=16, L=4, relu) ----
    k_prop1i<<<cdiv(N, 8), 256>>>(w1i, w1, w1r, b1, N);   // norms + layer0 + z
    k_prop48<<<cdiv(N, 8), 256>>>(w1r, b1, w1, 1, N);
    k_prop48<<<cdiv(N, 8), 256>>>(w1r, b1, w1, 1, N);
    k_prop48<<<cdiv(N, 8), 256>>>(w1r, b1, w1, 0, N);

    // ---- batchnorm + relu, conv2 init ----
    k_bnstats<<<232, 256>>>(N);
    k_conv2init<<<cdiv(N, 256), 256>>>(bg, bb, w2i, w2r, b2, N);

    // ---- conv2 (K=3, C=1, L=4, no act) + mean + sigmoid ----
    k_prop3<<<cdiv(N, 8), 256>>>(0, 0, 0, w2, out, N);
    k_prop3<<<cdiv(N, 8), 256>>>(1, 1, 0, w2, out, N);
    k_prop3<<<cdiv(N, 8), 256>>>(0, 1, 0, w2, out, N);
    k_prop3<<<cdiv(N, 8), 256>>>(1, 1, 1, w2, out, N);
}